// round 14
// baseline (speedup 1.0000x reference)
#include <cuda_runtime.h>
#include <cuda_bf16.h>
#include <math.h>
#include <stdint.h>

#define Bk 128
#define Sk 200
#define Dk 512
#define Hk 8
#define DFk 64
#define ROWS (Bk * Sk)          // 25600
#define SCALE 0.125f

typedef __nv_bfloat16 bf16;

// ---------------- device scratch ----------------
__device__ __align__(256) bf16 g_xhi[3][(size_t)ROWS * Dk];
__device__ __align__(256) bf16 g_xlo[3][(size_t)ROWS * Dk];
__device__ __align__(256) bf16 g_whi[4][(size_t)Dk * Dk];
__device__ __align__(256) bf16 g_wlo[4][(size_t)Dk * Dk];
__device__ __align__(256) bf16 g_Qh[(size_t)ROWS * Dk];   // [bh][s][64]
__device__ __align__(256) bf16 g_Ql[(size_t)ROWS * Dk];
__device__ __align__(256) bf16 g_Kh[(size_t)ROWS * Dk];
__device__ __align__(256) bf16 g_Kl[(size_t)ROWS * Dk];
__device__ __align__(256) bf16 g_Vh[(size_t)ROWS * Dk];   // [bh][df][s]
__device__ __align__(256) bf16 g_Vl[(size_t)ROWS * Dk];
__device__ __align__(256) bf16 g_chi[(size_t)ROWS * Dk];
__device__ __align__(256) bf16 g_clo[(size_t)ROWS * Dk];

// ---------------- helpers ----------------
#define MMA16816(d, a, b)                                                      \
    asm("mma.sync.aligned.m16n8k16.row.col.f32.bf16.bf16.f32 "                 \
        "{%0,%1,%2,%3}, {%4,%5,%6,%7}, {%8,%9}, {%0,%1,%2,%3};"                \
        : "+f"((d)[0]), "+f"((d)[1]), "+f"((d)[2]), "+f"((d)[3])               \
        : "r"((a)[0]), "r"((a)[1]), "r"((a)[2]), "r"((a)[3]),                  \
          "r"((b)[0]), "r"((b)[1]))

#define LDSM_X4(r0, r1, r2, r3, addr)                                          \
    asm volatile("ldmatrix.sync.aligned.m8n8.x4.shared.b16 {%0,%1,%2,%3}, [%4];" \
                 : "=r"(r0), "=r"(r1), "=r"(r2), "=r"(r3) : "r"(addr))

static __device__ __forceinline__ void cp_async16(uint32_t saddr, const void* gaddr) {
    asm volatile("cp.async.cg.shared.global [%0], [%1], 16;"
                 :: "r"(saddr), "l"(gaddr));
}
static __device__ __forceinline__ void cp_commit() {
    asm volatile("cp.async.commit_group;" ::: "memory");
}
template <int N>
static __device__ __forceinline__ void cp_wait() {
    asm volatile("cp.async.wait_group %0;" :: "n"(N) : "memory");
}
static __device__ __forceinline__ uint32_t packbf(float lo, float hi) {
    uint32_t r;
    asm("cvt.rn.bf16x2.f32 %0, %1, %2;" : "=r"(r) : "f"(hi), "f"(lo));
    return r;
}
static __device__ __forceinline__ float fast_exp(float x) {
    x = fmaxf(x, -87.0f);
    float t = fmaf(x, 1.4426950408889634f, 12582912.0f);
    float f = fmaf(x, 1.4426950408889634f, -(t - 12582912.0f));
    float z = f * 0.6931471805599453f;
    float r = fmaf(0.0013888889f, z, 0.0083333333f);
    r = fmaf(r, z, 0.041666667f);
    r = fmaf(r, z, 0.16666667f);
    r = fmaf(r, z, 0.5f);
    r = fmaf(r, z, 1.0f);
    r = fmaf(r, z, 1.0f);
    return r * __int_as_float((__float_as_int(t) + (127 - 0x4B400000)) << 23);
}
static __device__ __forceinline__ void splitpack(float p0, float p1,
                                                 uint32_t& hi, uint32_t& lo) {
    float h0 = __bfloat162float(__float2bfloat16(p0));
    float h1 = __bfloat162float(__float2bfloat16(p1));
    hi = packbf(h0, h1);
    lo = packbf(p0 - h0, p1 - h1);
}

// -- GEMM: 256 threads, CTA 128x128, BK=64, 2-stage, 1 barrier/chunk, 2 CTA/SM --
#define BKC 64
#define NCH (Dk / BKC)          // 8
#define PCH 144                 // row pitch bytes
#define SA_HI 0
#define SA_LO 18432
#define SB_HI 36864
#define SB_LO 55296
#define STG_B 73728
#define GEMM_SMEM (2 * STG_B)   // 147456

static __device__ __forceinline__ void load_chunk(
    char* stage, const bf16* __restrict__ Ah, const bf16* __restrict__ Al,
    const bf16* __restrict__ Bh, const bf16* __restrict__ Bl, int k0)
{
    const int tid = threadIdx.x;
    uint32_t sbase = (uint32_t)__cvta_generic_to_shared(stage);
#pragma unroll
    for (int j = 0; j < 16; j++) {
        const int idx = tid + j * 256;       // 0..4095
        if (idx < 2048) {                    // A: 2 splits x 128 rows x 8 c16
            const int sp = idx >> 10;
            const int w  = idx & 1023;
            const int r  = w >> 3;
            const int c  = w & 7;
            cp_async16(sbase + (sp ? SA_LO : SA_HI) + r * PCH + c * 16,
                       (sp ? Al : Ah) + (size_t)r * Dk + k0 + c * 8);
        } else {                             // B: 2 splits x 128 rows x 8 c16
            const int t  = idx - 2048;
            const int sp = t >> 10;
            const int w  = t & 1023;
            const int r  = w >> 3;
            const int c  = w & 7;
            cp_async16(sbase + (sp ? SB_LO : SB_HI) + r * PCH + c * 16,
                       (sp ? Bl : Bh) + (size_t)r * Dk + k0 + c * 8);
        }
    }
}

struct WAcc { float v[4][4][4]; };

static __device__ __forceinline__ void mma_mainloop(
    const bf16* __restrict__ Ahi, const bf16* __restrict__ Alo,
    const bf16* __restrict__ Bhi, const bf16* __restrict__ Blo,
    int m0, int n0, char* smem, WAcc& acc)
{
    const int tid   = threadIdx.x;
    const int wid   = tid >> 5;
    const int lane  = tid & 31;
    const int warpM = wid >> 2;          // 0..1
    const int warpN = wid & 3;           // 0..3
    const int lr    = lane & 7;
    const int lb3   = (lane >> 3) & 1;
    const int lb4   = (lane >> 4) & 1;

    const uint32_t abase = (uint32_t)((warpM * 64 + lr + lb3 * 8) * PCH + lb4 * 16);
    const uint32_t bbase = (uint32_t)((warpN * 32 + lr + lb4 * 8) * PCH + lb3 * 16);

    const bf16* Ah = Ahi + (size_t)m0 * Dk;
    const bf16* Al = Alo + (size_t)m0 * Dk;
    const bf16* Bh = Bhi + (size_t)n0 * Dk;
    const bf16* Bl = Blo + (size_t)n0 * Dk;

    uint32_t sbase = (uint32_t)__cvta_generic_to_shared(smem);

    load_chunk(smem, Ah, Al, Bh, Bl, 0);
    cp_commit();

    for (int c = 0; c < NCH; c++) {
        cp_wait<0>();
        __syncthreads();
        if (c + 1 < NCH) {
            load_chunk(smem + ((c + 1) & 1) * STG_B, Ah, Al, Bh, Bl, (c + 1) * BKC);
            cp_commit();
        }

        const uint32_t sg = sbase + (c & 1) * STG_B;
#pragma unroll
        for (int kh = 0; kh < 4; kh++) {
            uint32_t bh_[4][2], bl_[4][2];
#pragma unroll
            for (int nfp = 0; nfp < 2; nfp++) {
                const uint32_t bo = sg + bbase + nfp * (16 * PCH) + kh * 32;
                LDSM_X4(bh_[2 * nfp][0], bh_[2 * nfp][1],
                        bh_[2 * nfp + 1][0], bh_[2 * nfp + 1][1], bo + SB_HI);
                LDSM_X4(bl_[2 * nfp][0], bl_[2 * nfp][1],
                        bl_[2 * nfp + 1][0], bl_[2 * nfp + 1][1], bo + SB_LO);
            }
#pragma unroll
            for (int mf = 0; mf < 4; mf++) {
                const uint32_t ao = sg + abase + mf * (16 * PCH) + kh * 32;
                uint32_t ah[4], al[4];
                LDSM_X4(ah[0], ah[1], ah[2], ah[3], ao + SA_HI);
                LDSM_X4(al[0], al[1], al[2], al[3], ao + SA_LO);
#pragma unroll
                for (int nf = 0; nf < 4; nf++) MMA16816(acc.v[mf][nf], ah, bh_[nf]);
#pragma unroll
                for (int nf = 0; nf < 4; nf++) MMA16816(acc.v[mf][nf], ah, bl_[nf]);
#pragma unroll
                for (int nf = 0; nf < 4; nf++) MMA16816(acc.v[mf][nf], al, bh_[nf]);
            }
        }
    }
}

// ---------------- QKV projection: bf16 hi/lo epilogue ----------------
__global__ __launch_bounds__(256, 2)
void qkv_mma_kernel(const float* __restrict__ bq, const float* __restrict__ bk,
                    const float* __restrict__ bv)
{
    extern __shared__ char smem[];
    const int z  = blockIdx.z;
    const int m0 = blockIdx.y * 128;
    const int n0 = blockIdx.x * 128;

    WAcc acc;
#pragma unroll
    for (int a = 0; a < 4; a++)
#pragma unroll
        for (int b = 0; b < 4; b++)
#pragma unroll
            for (int cc = 0; cc < 4; cc++) acc.v[a][b][cc] = 0.f;

    mma_mainloop(g_xhi[z], g_xlo[z], g_whi[z], g_wlo[z], m0, n0, smem, acc);

    const float* bias = (z == 0) ? bq : (z == 1) ? bk : bv;
    bf16* oh = (z == 0) ? g_Qh : (z == 1) ? g_Kh : g_Vh;
    bf16* ol = (z == 0) ? g_Ql : (z == 1) ? g_Kl : g_Vl;

    const int lane  = threadIdx.x & 31;
    const int wid   = threadIdx.x >> 5;
    const int warpM = wid >> 2, warpN = wid & 3;
    const int g     = lane >> 2, q = lane & 3;

#pragma unroll
    for (int mf = 0; mf < 4; mf++) {
#pragma unroll
        for (int half = 0; half < 2; half++) {
            const int m  = m0 + warpM * 64 + mf * 16 + g + half * 8;
            const int bb = m / Sk;
            const int ss = m - bb * Sk;
#pragma unroll
            for (int nf = 0; nf < 4; nf++) {
                const int n  = n0 + warpN * 32 + nf * 8 + q * 2;
                const int hh = n >> 6;
                const int df = n & 63;
                float v0 = acc.v[mf][nf][half * 2 + 0] + bias[n];
                float v1 = acc.v[mf][nf][half * 2 + 1] + bias[n + 1];
                bf16 h0 = __float2bfloat16(v0);
                bf16 h1 = __float2bfloat16(v1);
                bf16 l0 = __float2bfloat16(v0 - __bfloat162float(h0));
                bf16 l1 = __float2bfloat16(v1 - __bfloat162float(h1));
                const size_t bh = (size_t)bb * Hk + hh;
                if (z < 2) {
                    const size_t o = (bh * Sk + ss) * DFk + df;
                    *(__nv_bfloat162*)&oh[o] = __halves2bfloat162(h0, h1);
                    *(__nv_bfloat162*)&ol[o] = __halves2bfloat162(l0, l1);
                } else {
                    const size_t o = (bh * DFk + df) * Sk + ss;
                    oh[o] = h0; oh[o + Sk] = h1;
                    ol[o] = l0; ol[o + Sk] = l1;
                }
            }
        }
    }
}

// ---------------- output projection ----------------
__global__ __launch_bounds__(256, 2)
void out_mma_kernel(const float* __restrict__ bo, float* __restrict__ out)
{
    extern __shared__ char smem[];
    const int m0 = blockIdx.y * 128;
    const int n0 = blockIdx.x * 128;

    WAcc acc;
#pragma unroll
    for (int a = 0; a < 4; a++)
#pragma unroll
        for (int b = 0; b < 4; b++)
#pragma unroll
            for (int cc = 0; cc < 4; cc++) acc.v[a][b][cc] = 0.f;

    mma_mainloop(g_chi, g_clo, g_whi[3], g_wlo[3], m0, n0, smem, acc);

    const int lane  = threadIdx.x & 31;
    const int wid   = threadIdx.x >> 5;
    const int warpM = wid >> 2, warpN = wid & 3;
    const int g     = lane >> 2, q = lane & 3;

#pragma unroll
    for (int mf = 0; mf < 4; mf++) {
#pragma unroll
        for (int half = 0; half < 2; half++) {
            const int m = m0 + warpM * 64 + mf * 16 + g + half * 8;
#pragma unroll
            for (int nf = 0; nf < 4; nf++) {
                const int n = n0 + warpN * 32 + nf * 8 + q * 2;
                float2 v;
                v.x = acc.v[mf][nf][half * 2 + 0] + bo[n];
                v.y = acc.v[mf][nf][half * 2 + 1] + bo[n + 1];
                *(float2*)(out + (size_t)m * Dk + n) = v;
            }
        }
    }
}

// ---------------- fused fp32 -> bf16 hi/lo split (all 7 tensors) ----------------
#define NX4 (ROWS * Dk / 4)
#define NW4 (Dk * Dk / 4)
#define CVT_TOT (3 * NX4 + 4 * NW4)

__global__ void cvt_all_kernel(const float* __restrict__ q, const float* __restrict__ k,
                               const float* __restrict__ v, const float* __restrict__ Wq,
                               const float* __restrict__ Wk, const float* __restrict__ Wv,
                               const float* __restrict__ Wo)
{
    const int i = blockIdx.x * blockDim.x + threadIdx.x;
    if (i >= CVT_TOT) return;
    const float* src;
    bf16 *hi, *lo;
    int off;
    if (i < 3 * NX4) {
        const int which = i / NX4;
        off = i - which * NX4;
        src = (which == 0) ? q : (which == 1) ? k : v;
        hi = g_xhi[which]; lo = g_xlo[which];
    } else {
        const int j = i - 3 * NX4;
        const int which = j / NW4;
        off = j - which * NW4;
        src = (which == 0) ? Wq : (which == 1) ? Wk : (which == 2) ? Wv : Wo;
        hi = g_whi[which]; lo = g_wlo[which];
    }
    float4 x = ((const float4*)src)[off];
    bf16 h0 = __float2bfloat16(x.x), h1 = __float2bfloat16(x.y);
    bf16 h2 = __float2bfloat16(x.z), h3 = __float2bfloat16(x.w);
    bf16 l0 = __float2bfloat16(x.x - __bfloat162float(h0));
    bf16 l1 = __float2bfloat16(x.y - __bfloat162float(h1));
    bf16 l2 = __float2bfloat16(x.z - __bfloat162float(h2));
    bf16 l3 = __float2bfloat16(x.w - __bfloat162float(h3));
    ((__nv_bfloat162*)hi)[2 * off]     = __halves2bfloat162(h0, h1);
    ((__nv_bfloat162*)hi)[2 * off + 1] = __halves2bfloat162(h2, h3);
    ((__nv_bfloat162*)lo)[2 * off]     = __halves2bfloat162(l0, l1);
    ((__nv_bfloat162*)lo)[2 * off + 1] = __halves2bfloat162(l2, l3);
}

// ------ balanced streaming tensor-core attention (unchanged from R13) ----------
#define SKH 0
#define SKL 14400
#define SVH 28800
#define SVL 42624
#define ATTN_SMEM 112896

__global__ __launch_bounds__(256, 2)
void attn_mma_kernel()
{
    extern __shared__ bf16 smb[];
    const int bh  = blockIdx.x;
    const int tid = threadIdx.x;
    uint32_t sb = (uint32_t)__cvta_generic_to_shared(smb);

    for (int u = tid; u < 2 * Sk * 8; u += 256) {
        int sp = (u >= Sk * 8), w2 = u - sp * Sk * 8, r = w2 >> 3, c = w2 & 7;
        cp_async16(sb + (uint32_t)((sp ? SKL : SKH) + r * 72 + c * 8) * 2,
                   (sp ? g_Kl : g_Kh) + ((size_t)bh * Sk + r) * DFk + c * 8);
    }
    for (int u = tid; u < 2 * 64 * 26; u += 256) {
        int sp = (u >= 64 * 26), w2 = u - sp * 64 * 26, r = w2 / 26, c = w2 - r * 26;
        int cc = min(c, 24);
        cp_async16(sb + (uint32_t)((sp ? SVL : SVH) + r * 216 + c * 8) * 2,
                   (sp ? g_Vl : g_Vh) + ((size_t)bh * DFk + r) * Sk + cc * 8);
    }
    cp_commit();

    const int w = tid >> 5, lane = tid & 31, g = lane >> 2, q = lane & 3;
    const int bbb = bh >> 3, hh = bh & 7;

    cp_wait<0>();
    __syncthreads();

    const int nb = (w >= 3) ? 2 : 1;
    for (int bi = 0; bi < nb; bi++) {
        const int blk = bi ? (w - 3) : (12 - w);
        const int qr0 = blk * 16 + g;
        const int qr1 = qr0 + 8;
        const int KCW = blk + 1;

        uint32_t qah[4][4], qal[4][4];
        {
            const int r1c = min(qr1, Sk - 1);
            const bf16* Qh0 = g_Qh + ((size_t)bh * Sk + qr0) * DFk;
            const bf16* Qh1 = g_Qh + ((size_t)bh * Sk + r1c) * DFk;
            const bf16* Ql0 = g_Ql + ((size_t)bh * Sk + qr0) * DFk;
            const bf16* Ql1 = g_Ql + ((size_t)bh * Sk + r1c) * DFk;
#pragma unroll
            for (int kc = 0; kc < 4; kc++) {
                const int col = 16 * kc + 2 * q;
                qah[kc][0] = *(const uint32_t*)(Qh0 + col);
                qah[kc][1] = *(const uint32_t*)(Qh1 + col);
                qah[kc][2] = *(const uint32_t*)(Qh0 + col + 8);
                qah[kc][3] = *(const uint32_t*)(Qh1 + col + 8);
                qal[kc][0] = *(const uint32_t*)(Ql0 + col);
                qal[kc][1] = *(const uint32_t*)(Ql1 + col);
                qal[kc][2] = *(const uint32_t*)(Ql0 + col + 8);
                qal[kc][3] = *(const uint32_t*)(Ql1 + col + 8);
            }
        }

        float oa[8][4];
#pragma unroll
        for (int nv = 0; nv < 8; nv++)
            oa[nv][0] = oa[nv][1] = oa[nv][2] = oa[nv][3] = 0.f;
        float sum0 = 0.f, sum1 = 0.f;

        for (int kc = 0; kc < KCW; kc++) {
            const bool d1 = (16 * kc + 8 < Sk);
            float s0[4] = {0.f, 0.f, 0.f, 0.f};
            float s1[4] = {0.f, 0.f, 0.f, 0.f};
#pragma unroll
            for (int dfc = 0; dfc < 4; dfc++) {
                const int o0 = (16 * kc + g) * 72 + 16 * dfc + 2 * q;
                uint32_t kb0[2], kl0[2], kb1[2], kl1[2];
                kb0[0] = *(const uint32_t*)&smb[SKH + o0];
                kb0[1] = *(const uint32_t*)&smb[SKH + o0 + 8];
                kl0[0] = *(const uint32_t*)&smb[SKL + o0];
                kl0[1] = *(const uint32_t*)&smb[SKL + o0 + 8];
                if (d1) {
                    const int o1 = o0 + 8 * 72;
                    kb1[0] = *(const uint32_t*)&smb[SKH + o1];
                    kb1[1] = *(const uint32_t*)&smb[SKH + o1 + 8];
                    kl1[0] = *(const uint32_t*)&smb[SKL + o1];
                    kl1[1] = *(const uint32_t*)&smb[SKL + o1 + 8];
                }
                MMA16816(s0, qah[dfc], kb0);
                if (d1) MMA16816(s1, qah[dfc], kb1);
                MMA16816(s0, qah[dfc], kl0);
                if (d1) MMA16816(s1, qah[dfc], kl1);
                MMA16816(s0, qal[dfc], kb0);
                if (d1) MMA16816(s1, qal[dfc], kb1);
            }
            const int k0 = 16 * kc + 2 * q;
            s0[0] = fast_exp((k0     <= qr0) ? s0[0] * SCALE : -1e30f);
            s0[1] = fast_exp((k0 + 1 <= qr0) ? s0[1] * SCALE : -1e30f);
            s0[2] = fast_exp((k0     <= qr1) ? s0[2] * SCALE : -1e30f);
            s0[3] = fast_exp((k0 + 1 <= qr1) ? s0[3] * SCALE : -1e30f);
            sum0 += s0[0] + s0[1];
            sum1 += s0[2] + s0[3];
            if (d1) {
                const int k1 = k0 + 8;
                s1[0] = fast_exp((k1     <= qr0) ? s1[0] * SCALE : -1e30f);
                s1[1] = fast_exp((k1 + 1 <= qr0) ? s1[1] * SCALE : -1e30f);
                s1[2] = fast_exp((k1     <= qr1) ? s1[2] * SCALE : -1e30f);
                s1[3] = fast_exp((k1 + 1 <= qr1) ? s1[3] * SCALE : -1e30f);
                sum0 += s1[0] + s1[1];
                sum1 += s1[2] + s1[3];
            }
            uint32_t ph[4], pl[4];
            splitpack(s0[0], s0[1], ph[0], pl[0]);
            splitpack(s0[2], s0[3], ph[1], pl[1]);
            if (d1) {
                splitpack(s1[0], s1[1], ph[2], pl[2]);
                splitpack(s1[2], s1[3], ph[3], pl[3]);
            } else {
                ph[2] = ph[3] = pl[2] = pl[3] = 0u;
            }
#pragma unroll
            for (int nvp = 0; nvp < 4; nvp++) {
                const int nv0 = 2 * nvp, nv1 = nv0 + 1;
                const int o0 = (8 * nv0 + g) * 216 + 16 * kc + 2 * q;
                const int o1 = o0 + 8 * 216;
                uint32_t vb0[2], vl0[2], vb1[2], vl1[2];
                vb0[0] = *(const uint32_t*)&smb[SVH + o0];
                vb0[1] = *(const uint32_t*)&smb[SVH + o0 + 8];
                vl0[0] = *(const uint32_t*)&smb[SVL + o0];
                vl0[1] = *(const uint32_t*)&smb[SVL + o0 + 8];
                vb1[0] = *(const uint32_t*)&smb[SVH + o1];
                vb1[1] = *(const uint32_t*)&smb[SVH + o1 + 8];
                vl1[0] = *(const uint32_t*)&smb[SVL + o1];
                vl1[1] = *(const uint32_t*)&smb[SVL + o1 + 8];
                MMA16816(oa[nv0], ph, vb0);
                MMA16816(oa[nv1], ph, vb1);
                MMA16816(oa[nv0], ph, vl0);
                MMA16816(oa[nv1], ph, vl1);
                MMA16816(oa[nv0], pl, vb0);
                MMA16816(oa[nv1], pl, vb1);
            }
        }

        sum0 += __shfl_xor_sync(0xFFFFFFFFu, sum0, 1);
        sum0 += __shfl_xor_sync(0xFFFFFFFFu, sum0, 2);
        sum1 += __shfl_xor_sync(0xFFFFFFFFu, sum1, 1);
        sum1 += __shfl_xor_sync(0xFFFFFFFFu, sum1, 2);
        const float inv0 = (qr0 == 0) ? 0.f : 1.f / fmaxf(sum0, 1e-37f);
        const float inv1 = 1.f / fmaxf(sum1, 1e-37f);

#pragma unroll
        for (int nv = 0; nv < 8; nv++) {
            const int df = 8 * nv + 2 * q;
            {
                const float x0 = oa[nv][0] * inv0, x1 = oa[nv][1] * inv0;
                const size_t o = ((size_t)bbb * Sk + qr0) * Dk + hh * 64 + df;
                bf16 a = __float2bfloat16(x0);
                bf16 b = __float2bfloat16(x1);
                *(__nv_bfloat162*)&g_chi[o] = __halves2bfloat162(a, b);
                *(__nv_bfloat162*)&g_clo[o] = __halves2bfloat162(
                    __float2bfloat16(x0 - __bfloat162float(a)),
                    __float2bfloat16(x1 - __bfloat162float(b)));
            }
            if (qr1 < Sk) {
                const float x0 = oa[nv][2] * inv1, x1 = oa[nv][3] * inv1;
                const size_t o = ((size_t)bbb * Sk + qr1) * Dk + hh * 64 + df;
                bf16 a = __float2bfloat16(x0);
                bf16 b = __float2bfloat16(x1);
                *(__nv_bfloat162*)&g_chi[o] = __halves2bfloat162(a, b);
                *(__nv_bfloat162*)&g_clo[o] = __halves2bfloat162(
                    __float2bfloat16(x0 - __bfloat162float(a)),
                    __float2bfloat16(x1 - __bfloat162float(b)));
            }
        }
    }
}

// ---------------- launch ----------------
extern "C" void kernel_launch(void* const* d_in, const int* in_sizes, int n_in,
                              void* d_out, int out_size)
{
    const float* q  = (const float*)d_in[0];
    const float* k  = (const float*)d_in[1];
    const float* v  = (const float*)d_in[2];
    const float* Wq = (const float*)d_in[3];
    const float* bq = (const float*)d_in[4];
    const float* Wk = (const float*)d_in[5];
    const float* bk = (const float*)d_in[6];
    const float* Wv = (const float*)d_in[7];
    const float* bv = (const float*)d_in[8];
    const float* Wo = (const float*)d_in[9];
    const float* bo = (const float*)d_in[10];
    float* out = (float*)d_out;

    cvt_all_kernel<<<(CVT_TOT + 255) / 256, 256>>>(q, k, v, Wq, Wk, Wv, Wo);

    cudaFuncSetAttribute(qkv_mma_kernel, cudaFuncAttributeMaxDynamicSharedMemorySize,
                         GEMM_SMEM);
    qkv_mma_kernel<<<dim3(Dk / 128, ROWS / 128, 3), 256, GEMM_SMEM>>>(bq, bk, bv);

    cudaFuncSetAttribute(attn_mma_kernel, cudaFuncAttributeMaxDynamicSharedMemorySize,
                         ATTN_SMEM);
    attn_mma_kernel<<<Bk * Hk, 256, ATTN_SMEM>>>();

    cudaFuncSetAttribute(out_mma_kernel, cudaFuncAttributeMaxDynamicSharedMemorySize,
                         GEMM_SMEM);
    out_mma_kernel<<<dim3(Dk / 128, ROWS / 128, 1), 256, GEMM_SMEM>>>(bo, out);
}

// round 15
// speedup vs baseline: 1.1033x; 1.1033x over previous
#include <cuda_runtime.h>
#include <cuda_bf16.h>
#include <math.h>
#include <stdint.h>

#define Bk 128
#define Sk 200
#define Dk 512
#define Hk 8
#define DFk 64
#define ROWS (Bk * Sk)          // 25600
#define SCALE 0.125f

typedef __nv_bfloat16 bf16;

// ---------------- device scratch ----------------
__device__ __align__(256) bf16 g_xhi[3][(size_t)ROWS * Dk];
__device__ __align__(256) bf16 g_xlo[3][(size_t)ROWS * Dk];
__device__ __align__(256) bf16 g_whi[4][(size_t)Dk * Dk];
__device__ __align__(256) bf16 g_wlo[4][(size_t)Dk * Dk];
__device__ __align__(256) bf16 g_Qh[(size_t)ROWS * Dk];   // [bh][s][64]
__device__ __align__(256) bf16 g_Ql[(size_t)ROWS * Dk];
__device__ __align__(256) bf16 g_Kh[(size_t)ROWS * Dk];
__device__ __align__(256) bf16 g_Kl[(size_t)ROWS * Dk];
__device__ __align__(256) bf16 g_Vh[(size_t)ROWS * Dk];   // [bh][df][s]
__device__ __align__(256) bf16 g_Vl[(size_t)ROWS * Dk];
__device__ __align__(256) bf16 g_chi[(size_t)ROWS * Dk];
__device__ __align__(256) bf16 g_clo[(size_t)ROWS * Dk];

// ---------------- helpers ----------------
#define MMA16816(d, a, b)                                                      \
    asm("mma.sync.aligned.m16n8k16.row.col.f32.bf16.bf16.f32 "                 \
        "{%0,%1,%2,%3}, {%4,%5,%6,%7}, {%8,%9}, {%0,%1,%2,%3};"                \
        : "+f"((d)[0]), "+f"((d)[1]), "+f"((d)[2]), "+f"((d)[3])               \
        : "r"((a)[0]), "r"((a)[1]), "r"((a)[2]), "r"((a)[3]),                  \
          "r"((b)[0]), "r"((b)[1]))

#define LDSM_X4(r0, r1, r2, r3, addr)                                          \
    asm volatile("ldmatrix.sync.aligned.m8n8.x4.shared.b16 {%0,%1,%2,%3}, [%4];" \
                 : "=r"(r0), "=r"(r1), "=r"(r2), "=r"(r3) : "r"(addr))

static __device__ __forceinline__ void cp_async16(uint32_t saddr, const void* gaddr) {
    asm volatile("cp.async.cg.shared.global [%0], [%1], 16;"
                 :: "r"(saddr), "l"(gaddr));
}
static __device__ __forceinline__ void cp_commit() {
    asm volatile("cp.async.commit_group;" ::: "memory");
}
template <int N>
static __device__ __forceinline__ void cp_wait() {
    asm volatile("cp.async.wait_group %0;" :: "n"(N) : "memory");
}
static __device__ __forceinline__ uint32_t packbf(float lo, float hi) {
    uint32_t r;
    asm("cvt.rn.bf16x2.f32 %0, %1, %2;" : "=r"(r) : "f"(hi), "f"(lo));
    return r;
}
static __device__ __forceinline__ float fast_exp(float x) {
    x = fmaxf(x, -87.0f);
    float t = fmaf(x, 1.4426950408889634f, 12582912.0f);
    float f = fmaf(x, 1.4426950408889634f, -(t - 12582912.0f));
    float z = f * 0.6931471805599453f;
    float r = fmaf(0.0013888889f, z, 0.0083333333f);
    r = fmaf(r, z, 0.041666667f);
    r = fmaf(r, z, 0.16666667f);
    r = fmaf(r, z, 0.5f);
    r = fmaf(r, z, 1.0f);
    r = fmaf(r, z, 1.0f);
    return r * __int_as_float((__float_as_int(t) + (127 - 0x4B400000)) << 23);
}
static __device__ __forceinline__ void splitpack(float p0, float p1,
                                                 uint32_t& hi, uint32_t& lo) {
    float h0 = __bfloat162float(__float2bfloat16(p0));
    float h1 = __bfloat162float(__float2bfloat16(p1));
    hi = packbf(h0, h1);
    lo = packbf(p0 - h0, p1 - h1);
}

// -- GEMM: 256 threads, CTA 128x128, BK=32, 2-stage, TRUE 2 CTA/SM (82 KB) ----
#define BKC 32
#define NCH (Dk / BKC)          // 16
#define PCH 80                  // row pitch bytes (64 data + 16 pad)
#define SA_HI 0
#define SA_LO 10240
#define SB_HI 20480
#define SB_LO 30720
#define STG_B 40960
#define GEMM_SMEM (2 * STG_B)   // 81920

static __device__ __forceinline__ void load_chunk(
    char* stage, const bf16* __restrict__ Ah, const bf16* __restrict__ Al,
    const bf16* __restrict__ Bh, const bf16* __restrict__ Bl, int k0)
{
    const int tid = threadIdx.x;
    uint32_t sbase = (uint32_t)__cvta_generic_to_shared(stage);
#pragma unroll
    for (int j = 0; j < 8; j++) {
        const int idx = tid + j * 256;       // 0..2047
        if (idx < 1024) {                    // A: 2 splits x 128 rows x 4 c16
            const int sp = idx >> 9;
            const int w  = idx & 511;
            const int r  = w >> 2;
            const int c  = w & 3;
            cp_async16(sbase + (sp ? SA_LO : SA_HI) + r * PCH + c * 16,
                       (sp ? Al : Ah) + (size_t)r * Dk + k0 + c * 8);
        } else {                             // B: 2 splits x 128 rows x 4 c16
            const int t  = idx - 1024;
            const int sp = t >> 9;
            const int w  = t & 511;
            const int r  = w >> 2;
            const int c  = w & 3;
            cp_async16(sbase + (sp ? SB_LO : SB_HI) + r * PCH + c * 16,
                       (sp ? Bl : Bh) + (size_t)r * Dk + k0 + c * 8);
        }
    }
}

struct WAcc { float v[4][4][4]; };

static __device__ __forceinline__ void mma_mainloop(
    const bf16* __restrict__ Ahi, const bf16* __restrict__ Alo,
    const bf16* __restrict__ Bhi, const bf16* __restrict__ Blo,
    int m0, int n0, char* smem, WAcc& acc)
{
    const int tid   = threadIdx.x;
    const int wid   = tid >> 5;
    const int lane  = tid & 31;
    const int warpM = wid >> 2;          // 0..1
    const int warpN = wid & 3;           // 0..3
    const int lr    = lane & 7;
    const int lb3   = (lane >> 3) & 1;
    const int lb4   = (lane >> 4) & 1;

    const uint32_t abase = (uint32_t)((warpM * 64 + lr + lb3 * 8) * PCH + lb4 * 16);
    const uint32_t bbase = (uint32_t)((warpN * 32 + lr + lb4 * 8) * PCH + lb3 * 16);

    const bf16* Ah = Ahi + (size_t)m0 * Dk;
    const bf16* Al = Alo + (size_t)m0 * Dk;
    const bf16* Bh = Bhi + (size_t)n0 * Dk;
    const bf16* Bl = Blo + (size_t)n0 * Dk;

    uint32_t sbase = (uint32_t)__cvta_generic_to_shared(smem);

    load_chunk(smem, Ah, Al, Bh, Bl, 0);
    cp_commit();

    for (int c = 0; c < NCH; c++) {
        cp_wait<0>();
        __syncthreads();
        if (c + 1 < NCH) {
            load_chunk(smem + ((c + 1) & 1) * STG_B, Ah, Al, Bh, Bl, (c + 1) * BKC);
            cp_commit();
        }

        const uint32_t sg = sbase + (c & 1) * STG_B;
#pragma unroll
        for (int kh = 0; kh < 2; kh++) {
            uint32_t bh_[4][2], bl_[4][2];
#pragma unroll
            for (int nfp = 0; nfp < 2; nfp++) {
                const uint32_t bo = sg + bbase + nfp * (16 * PCH) + kh * 32;
                LDSM_X4(bh_[2 * nfp][0], bh_[2 * nfp][1],
                        bh_[2 * nfp + 1][0], bh_[2 * nfp + 1][1], bo + SB_HI);
                LDSM_X4(bl_[2 * nfp][0], bl_[2 * nfp][1],
                        bl_[2 * nfp + 1][0], bl_[2 * nfp + 1][1], bo + SB_LO);
            }
#pragma unroll
            for (int mf = 0; mf < 4; mf++) {
                const uint32_t ao = sg + abase + mf * (16 * PCH) + kh * 32;
                uint32_t ah[4], al[4];
                LDSM_X4(ah[0], ah[1], ah[2], ah[3], ao + SA_HI);
                LDSM_X4(al[0], al[1], al[2], al[3], ao + SA_LO);
#pragma unroll
                for (int nf = 0; nf < 4; nf++) MMA16816(acc.v[mf][nf], ah, bh_[nf]);
#pragma unroll
                for (int nf = 0; nf < 4; nf++) MMA16816(acc.v[mf][nf], ah, bl_[nf]);
#pragma unroll
                for (int nf = 0; nf < 4; nf++) MMA16816(acc.v[mf][nf], al, bh_[nf]);
            }
        }
    }
}

// ---------------- QKV projection: bf16 hi/lo epilogue ----------------
__global__ __launch_bounds__(256, 2)
void qkv_mma_kernel(const float* __restrict__ bq, const float* __restrict__ bk,
                    const float* __restrict__ bv)
{
    extern __shared__ char smem[];
    const int z  = blockIdx.z;
    const int m0 = blockIdx.y * 128;
    const int n0 = blockIdx.x * 128;

    WAcc acc;
#pragma unroll
    for (int a = 0; a < 4; a++)
#pragma unroll
        for (int b = 0; b < 4; b++)
#pragma unroll
            for (int cc = 0; cc < 4; cc++) acc.v[a][b][cc] = 0.f;

    mma_mainloop(g_xhi[z], g_xlo[z], g_whi[z], g_wlo[z], m0, n0, smem, acc);

    const float* bias = (z == 0) ? bq : (z == 1) ? bk : bv;
    bf16* oh = (z == 0) ? g_Qh : (z == 1) ? g_Kh : g_Vh;
    bf16* ol = (z == 0) ? g_Ql : (z == 1) ? g_Kl : g_Vl;

    const int lane  = threadIdx.x & 31;
    const int wid   = threadIdx.x >> 5;
    const int warpM = wid >> 2, warpN = wid & 3;
    const int g     = lane >> 2, q = lane & 3;

#pragma unroll
    for (int mf = 0; mf < 4; mf++) {
#pragma unroll
        for (int half = 0; half < 2; half++) {
            const int m  = m0 + warpM * 64 + mf * 16 + g + half * 8;
            const int bb = m / Sk;
            const int ss = m - bb * Sk;
#pragma unroll
            for (int nf = 0; nf < 4; nf++) {
                const int n  = n0 + warpN * 32 + nf * 8 + q * 2;
                const int hh = n >> 6;
                const int df = n & 63;
                float v0 = acc.v[mf][nf][half * 2 + 0] + bias[n];
                float v1 = acc.v[mf][nf][half * 2 + 1] + bias[n + 1];
                bf16 h0 = __float2bfloat16(v0);
                bf16 h1 = __float2bfloat16(v1);
                bf16 l0 = __float2bfloat16(v0 - __bfloat162float(h0));
                bf16 l1 = __float2bfloat16(v1 - __bfloat162float(h1));
                const size_t bh = (size_t)bb * Hk + hh;
                if (z < 2) {
                    const size_t o = (bh * Sk + ss) * DFk + df;
                    *(__nv_bfloat162*)&oh[o] = __halves2bfloat162(h0, h1);
                    *(__nv_bfloat162*)&ol[o] = __halves2bfloat162(l0, l1);
                } else {
                    const size_t o = (bh * DFk + df) * Sk + ss;
                    oh[o] = h0; oh[o + Sk] = h1;
                    ol[o] = l0; ol[o + Sk] = l1;
                }
            }
        }
    }
}

// ---------------- output projection ----------------
__global__ __launch_bounds__(256, 2)
void out_mma_kernel(const float* __restrict__ bo, float* __restrict__ out)
{
    extern __shared__ char smem[];
    const int m0 = blockIdx.y * 128;
    const int n0 = blockIdx.x * 128;

    WAcc acc;
#pragma unroll
    for (int a = 0; a < 4; a++)
#pragma unroll
        for (int b = 0; b < 4; b++)
#pragma unroll
            for (int cc = 0; cc < 4; cc++) acc.v[a][b][cc] = 0.f;

    mma_mainloop(g_chi, g_clo, g_whi[3], g_wlo[3], m0, n0, smem, acc);

    const int lane  = threadIdx.x & 31;
    const int wid   = threadIdx.x >> 5;
    const int warpM = wid >> 2, warpN = wid & 3;
    const int g     = lane >> 2, q = lane & 3;

#pragma unroll
    for (int mf = 0; mf < 4; mf++) {
#pragma unroll
        for (int half = 0; half < 2; half++) {
            const int m = m0 + warpM * 64 + mf * 16 + g + half * 8;
#pragma unroll
            for (int nf = 0; nf < 4; nf++) {
                const int n = n0 + warpN * 32 + nf * 8 + q * 2;
                float2 v;
                v.x = acc.v[mf][nf][half * 2 + 0] + bo[n];
                v.y = acc.v[mf][nf][half * 2 + 1] + bo[n + 1];
                *(float2*)(out + (size_t)m * Dk + n) = v;
            }
        }
    }
}

// ---------------- fused fp32 -> bf16 hi/lo split (all 7 tensors) ----------------
#define NX4 (ROWS * Dk / 4)
#define NW4 (Dk * Dk / 4)
#define CVT_TOT (3 * NX4 + 4 * NW4)

__global__ void cvt_all_kernel(const float* __restrict__ q, const float* __restrict__ k,
                               const float* __restrict__ v, const float* __restrict__ Wq,
                               const float* __restrict__ Wk, const float* __restrict__ Wv,
                               const float* __restrict__ Wo)
{
    const int i = blockIdx.x * blockDim.x + threadIdx.x;
    if (i >= CVT_TOT) return;
    const float* src;
    bf16 *hi, *lo;
    int off;
    if (i < 3 * NX4) {
        const int which = i / NX4;
        off = i - which * NX4;
        src = (which == 0) ? q : (which == 1) ? k : v;
        hi = g_xhi[which]; lo = g_xlo[which];
    } else {
        const int j = i - 3 * NX4;
        const int which = j / NW4;
        off = j - which * NW4;
        src = (which == 0) ? Wq : (which == 1) ? Wk : (which == 2) ? Wv : Wo;
        hi = g_whi[which]; lo = g_wlo[which];
    }
    float4 x = ((const float4*)src)[off];
    bf16 h0 = __float2bfloat16(x.x), h1 = __float2bfloat16(x.y);
    bf16 h2 = __float2bfloat16(x.z), h3 = __float2bfloat16(x.w);
    bf16 l0 = __float2bfloat16(x.x - __bfloat162float(h0));
    bf16 l1 = __float2bfloat16(x.y - __bfloat162float(h1));
    bf16 l2 = __float2bfloat16(x.z - __bfloat162float(h2));
    bf16 l3 = __float2bfloat16(x.w - __bfloat162float(h3));
    ((__nv_bfloat162*)hi)[2 * off]     = __halves2bfloat162(h0, h1);
    ((__nv_bfloat162*)hi)[2 * off + 1] = __halves2bfloat162(h2, h3);
    ((__nv_bfloat162*)lo)[2 * off]     = __halves2bfloat162(l0, l1);
    ((__nv_bfloat162*)lo)[2 * off + 1] = __halves2bfloat162(l2, l3);
}

// ------ balanced streaming tensor-core attention (unchanged from R13) ----------
#define SKH 0
#define SKL 14400
#define SVH 28800
#define SVL 42624
#define ATTN_SMEM 112896

__global__ __launch_bounds__(256, 2)
void attn_mma_kernel()
{
    extern __shared__ bf16 smb[];
    const int bh  = blockIdx.x;
    const int tid = threadIdx.x;
    uint32_t sb = (uint32_t)__cvta_generic_to_shared(smb);

    for (int u = tid; u < 2 * Sk * 8; u += 256) {
        int sp = (u >= Sk * 8), w2 = u - sp * Sk * 8, r = w2 >> 3, c = w2 & 7;
        cp_async16(sb + (uint32_t)((sp ? SKL : SKH) + r * 72 + c * 8) * 2,
                   (sp ? g_Kl : g_Kh) + ((size_t)bh * Sk + r) * DFk + c * 8);
    }
    for (int u = tid; u < 2 * 64 * 26; u += 256) {
        int sp = (u >= 64 * 26), w2 = u - sp * 64 * 26, r = w2 / 26, c = w2 - r * 26;
        int cc = min(c, 24);
        cp_async16(sb + (uint32_t)((sp ? SVL : SVH) + r * 216 + c * 8) * 2,
                   (sp ? g_Vl : g_Vh) + ((size_t)bh * DFk + r) * Sk + cc * 8);
    }
    cp_commit();

    const int w = tid >> 5, lane = tid & 31, g = lane >> 2, q = lane & 3;
    const int bbb = bh >> 3, hh = bh & 7;

    cp_wait<0>();
    __syncthreads();

    const int nb = (w >= 3) ? 2 : 1;
    for (int bi = 0; bi < nb; bi++) {
        const int blk = bi ? (w - 3) : (12 - w);
        const int qr0 = blk * 16 + g;
        const int qr1 = qr0 + 8;
        const int KCW = blk + 1;

        uint32_t qah[4][4], qal[4][4];
        {
            const int r1c = min(qr1, Sk - 1);
            const bf16* Qh0 = g_Qh + ((size_t)bh * Sk + qr0) * DFk;
            const bf16* Qh1 = g_Qh + ((size_t)bh * Sk + r1c) * DFk;
            const bf16* Ql0 = g_Ql + ((size_t)bh * Sk + qr0) * DFk;
            const bf16* Ql1 = g_Ql + ((size_t)bh * Sk + r1c) * DFk;
#pragma unroll
            for (int kc = 0; kc < 4; kc++) {
                const int col = 16 * kc + 2 * q;
                qah[kc][0] = *(const uint32_t*)(Qh0 + col);
                qah[kc][1] = *(const uint32_t*)(Qh1 + col);
                qah[kc][2] = *(const uint32_t*)(Qh0 + col + 8);
                qah[kc][3] = *(const uint32_t*)(Qh1 + col + 8);
                qal[kc][0] = *(const uint32_t*)(Ql0 + col);
                qal[kc][1] = *(const uint32_t*)(Ql1 + col);
                qal[kc][2] = *(const uint32_t*)(Ql0 + col + 8);
                qal[kc][3] = *(const uint32_t*)(Ql1 + col + 8);
            }
        }

        float oa[8][4];
#pragma unroll
        for (int nv = 0; nv < 8; nv++)
            oa[nv][0] = oa[nv][1] = oa[nv][2] = oa[nv][3] = 0.f;
        float sum0 = 0.f, sum1 = 0.f;

        for (int kc = 0; kc < KCW; kc++) {
            const bool d1 = (16 * kc + 8 < Sk);
            float s0[4] = {0.f, 0.f, 0.f, 0.f};
            float s1[4] = {0.f, 0.f, 0.f, 0.f};
#pragma unroll
            for (int dfc = 0; dfc < 4; dfc++) {
                const int o0 = (16 * kc + g) * 72 + 16 * dfc + 2 * q;
                uint32_t kb0[2], kl0[2], kb1[2], kl1[2];
                kb0[0] = *(const uint32_t*)&smb[SKH + o0];
                kb0[1] = *(const uint32_t*)&smb[SKH + o0 + 8];
                kl0[0] = *(const uint32_t*)&smb[SKL + o0];
                kl0[1] = *(const uint32_t*)&smb[SKL + o0 + 8];
                if (d1) {
                    const int o1 = o0 + 8 * 72;
                    kb1[0] = *(const uint32_t*)&smb[SKH + o1];
                    kb1[1] = *(const uint32_t*)&smb[SKH + o1 + 8];
                    kl1[0] = *(const uint32_t*)&smb[SKL + o1];
                    kl1[1] = *(const uint32_t*)&smb[SKL + o1 + 8];
                }
                MMA16816(s0, qah[dfc], kb0);
                if (d1) MMA16816(s1, qah[dfc], kb1);
                MMA16816(s0, qah[dfc], kl0);
                if (d1) MMA16816(s1, qah[dfc], kl1);
                MMA16816(s0, qal[dfc], kb0);
                if (d1) MMA16816(s1, qal[dfc], kb1);
            }
            const int k0 = 16 * kc + 2 * q;
            s0[0] = fast_exp((k0     <= qr0) ? s0[0] * SCALE : -1e30f);
            s0[1] = fast_exp((k0 + 1 <= qr0) ? s0[1] * SCALE : -1e30f);
            s0[2] = fast_exp((k0     <= qr1) ? s0[2] * SCALE : -1e30f);
            s0[3] = fast_exp((k0 + 1 <= qr1) ? s0[3] * SCALE : -1e30f);
            sum0 += s0[0] + s0[1];
            sum1 += s0[2] + s0[3];
            if (d1) {
                const int k1 = k0 + 8;
                s1[0] = fast_exp((k1     <= qr0) ? s1[0] * SCALE : -1e30f);
                s1[1] = fast_exp((k1 + 1 <= qr0) ? s1[1] * SCALE : -1e30f);
                s1[2] = fast_exp((k1     <= qr1) ? s1[2] * SCALE : -1e30f);
                s1[3] = fast_exp((k1 + 1 <= qr1) ? s1[3] * SCALE : -1e30f);
                sum0 += s1[0] + s1[1];
                sum1 += s1[2] + s1[3];
            }
            uint32_t ph[4], pl[4];
            splitpack(s0[0], s0[1], ph[0], pl[0]);
            splitpack(s0[2], s0[3], ph[1], pl[1]);
            if (d1) {
                splitpack(s1[0], s1[1], ph[2], pl[2]);
                splitpack(s1[2], s1[3], ph[3], pl[3]);
            } else {
                ph[2] = ph[3] = pl[2] = pl[3] = 0u;
            }
#pragma unroll
            for (int nvp = 0; nvp < 4; nvp++) {
                const int nv0 = 2 * nvp, nv1 = nv0 + 1;
                const int o0 = (8 * nv0 + g) * 216 + 16 * kc + 2 * q;
                const int o1 = o0 + 8 * 216;
                uint32_t vb0[2], vl0[2], vb1[2], vl1[2];
                vb0[0] = *(const uint32_t*)&smb[SVH + o0];
                vb0[1] = *(const uint32_t*)&smb[SVH + o0 + 8];
                vl0[0] = *(const uint32_t*)&smb[SVL + o0];
                vl0[1] = *(const uint32_t*)&smb[SVL + o0 + 8];
                vb1[0] = *(const uint32_t*)&smb[SVH + o1];
                vb1[1] = *(const uint32_t*)&smb[SVH + o1 + 8];
                vl1[0] = *(const uint32_t*)&smb[SVL + o1];
                vl1[1] = *(const uint32_t*)&smb[SVL + o1 + 8];
                MMA16816(oa[nv0], ph, vb0);
                MMA16816(oa[nv1], ph, vb1);
                MMA16816(oa[nv0], ph, vl0);
                MMA16816(oa[nv1], ph, vl1);
                MMA16816(oa[nv0], pl, vb0);
                MMA16816(oa[nv1], pl, vb1);
            }
        }

        sum0 += __shfl_xor_sync(0xFFFFFFFFu, sum0, 1);
        sum0 += __shfl_xor_sync(0xFFFFFFFFu, sum0, 2);
        sum1 += __shfl_xor_sync(0xFFFFFFFFu, sum1, 1);
        sum1 += __shfl_xor_sync(0xFFFFFFFFu, sum1, 2);
        const float inv0 = (qr0 == 0) ? 0.f : 1.f / fmaxf(sum0, 1e-37f);
        const float inv1 = 1.f / fmaxf(sum1, 1e-37f);

#pragma unroll
        for (int nv = 0; nv < 8; nv++) {
            const int df = 8 * nv + 2 * q;
            {
                const float x0 = oa[nv][0] * inv0, x1 = oa[nv][1] * inv0;
                const size_t o = ((size_t)bbb * Sk + qr0) * Dk + hh * 64 + df;
                bf16 a = __float2bfloat16(x0);
                bf16 b = __float2bfloat16(x1);
                *(__nv_bfloat162*)&g_chi[o] = __halves2bfloat162(a, b);
                *(__nv_bfloat162*)&g_clo[o] = __halves2bfloat162(
                    __float2bfloat16(x0 - __bfloat162float(a)),
                    __float2bfloat16(x1 - __bfloat162float(b)));
            }
            if (qr1 < Sk) {
                const float x0 = oa[nv][2] * inv1, x1 = oa[nv][3] * inv1;
                const size_t o = ((size_t)bbb * Sk + qr1) * Dk + hh * 64 + df;
                bf16 a = __float2bfloat16(x0);
                bf16 b = __float2bfloat16(x1);
                *(__nv_bfloat162*)&g_chi[o] = __halves2bfloat162(a, b);
                *(__nv_bfloat162*)&g_clo[o] = __halves2bfloat162(
                    __float2bfloat16(x0 - __bfloat162float(a)),
                    __float2bfloat16(x1 - __bfloat162float(b)));
            }
        }
    }
}

// ---------------- launch ----------------
extern "C" void kernel_launch(void* const* d_in, const int* in_sizes, int n_in,
                              void* d_out, int out_size)
{
    const float* q  = (const float*)d_in[0];
    const float* k  = (const float*)d_in[1];
    const float* v  = (const float*)d_in[2];
    const float* Wq = (const float*)d_in[3];
    const float* bq = (const float*)d_in[4];
    const float* Wk = (const float*)d_in[5];
    const float* bk = (const float*)d_in[6];
    const float* Wv = (const float*)d_in[7];
    const float* bv = (const float*)d_in[8];
    const float* Wo = (const float*)d_in[9];
    const float* bo = (const float*)d_in[10];
    float* out = (float*)d_out;

    cvt_all_kernel<<<(CVT_TOT + 255) / 256, 256>>>(q, k, v, Wq, Wk, Wv, Wo);

    cudaFuncSetAttribute(qkv_mma_kernel, cudaFuncAttributeMaxDynamicSharedMemorySize,
                         GEMM_SMEM);
    qkv_mma_kernel<<<dim3(Dk / 128, ROWS / 128, 3), 256, GEMM_SMEM>>>(bq, bk, bv);

    cudaFuncSetAttribute(attn_mma_kernel, cudaFuncAttributeMaxDynamicSharedMemorySize,
                         ATTN_SMEM);
    attn_mma_kernel<<<Bk * Hk, 256, ATTN_SMEM>>>();

    cudaFuncSetAttribute(out_mma_kernel, cudaFuncAttributeMaxDynamicSharedMemorySize,
                         GEMM_SMEM);
    out_mma_kernel<<<dim3(Dk / 128, ROWS / 128, 1), 256, GEMM_SMEM>>>(bo, out);
}

// round 16
// speedup vs baseline: 1.1268x; 1.0213x over previous
#include <cuda_runtime.h>
#include <cuda_bf16.h>
#include <math.h>
#include <stdint.h>

#define Bk 128
#define Sk 200
#define Dk 512
#define Hk 8
#define DFk 64
#define ROWS (Bk * Sk)          // 25600
#define SCALE 0.125f

typedef __nv_bfloat16 bf16;

// ---------------- device scratch ----------------
__device__ __align__(256) bf16 g_xhi[3][(size_t)ROWS * Dk];
__device__ __align__(256) bf16 g_xlo[3][(size_t)ROWS * Dk];
__device__ __align__(256) bf16 g_whi[4][(size_t)Dk * Dk];
__device__ __align__(256) bf16 g_wlo[4][(size_t)Dk * Dk];
__device__ __align__(256) bf16 g_Qh[(size_t)ROWS * Dk];   // [bh][s][64]
__device__ __align__(256) bf16 g_Ql[(size_t)ROWS * Dk];
__device__ __align__(256) bf16 g_Kh[(size_t)ROWS * Dk];
__device__ __align__(256) bf16 g_Kl[(size_t)ROWS * Dk];
__device__ __align__(256) bf16 g_Vh[(size_t)ROWS * Dk];   // [bh][df][s]
__device__ __align__(256) bf16 g_Vl[(size_t)ROWS * Dk];
__device__ __align__(256) bf16 g_chi[(size_t)ROWS * Dk];
__device__ __align__(256) bf16 g_clo[(size_t)ROWS * Dk];

// ---------------- helpers ----------------
#define MMA16816(d, a, b)                                                      \
    asm("mma.sync.aligned.m16n8k16.row.col.f32.bf16.bf16.f32 "                 \
        "{%0,%1,%2,%3}, {%4,%5,%6,%7}, {%8,%9}, {%0,%1,%2,%3};"                \
        : "+f"((d)[0]), "+f"((d)[1]), "+f"((d)[2]), "+f"((d)[3])               \
        : "r"((a)[0]), "r"((a)[1]), "r"((a)[2]), "r"((a)[3]),                  \
          "r"((b)[0]), "r"((b)[1]))

#define LDSM_X4(r0, r1, r2, r3, addr)                                          \
    asm volatile("ldmatrix.sync.aligned.m8n8.x4.shared.b16 {%0,%1,%2,%3}, [%4];" \
                 : "=r"(r0), "=r"(r1), "=r"(r2), "=r"(r3) : "r"(addr))

static __device__ __forceinline__ void cp_async16(uint32_t saddr, const void* gaddr) {
    asm volatile("cp.async.cg.shared.global [%0], [%1], 16;"
                 :: "r"(saddr), "l"(gaddr));
}
static __device__ __forceinline__ void cp_commit() {
    asm volatile("cp.async.commit_group;" ::: "memory");
}
template <int N>
static __device__ __forceinline__ void cp_wait() {
    asm volatile("cp.async.wait_group %0;" :: "n"(N) : "memory");
}
static __device__ __forceinline__ uint32_t packbf(float lo, float hi) {
    uint32_t r;
    asm("cvt.rn.bf16x2.f32 %0, %1, %2;" : "=r"(r) : "f"(hi), "f"(lo));
    return r;
}
static __device__ __forceinline__ float fast_exp(float x) {
    x = fmaxf(x, -87.0f);
    float t = fmaf(x, 1.4426950408889634f, 12582912.0f);
    float f = fmaf(x, 1.4426950408889634f, -(t - 12582912.0f));
    float z = f * 0.6931471805599453f;
    float r = fmaf(0.0013888889f, z, 0.0083333333f);
    r = fmaf(r, z, 0.041666667f);
    r = fmaf(r, z, 0.16666667f);
    r = fmaf(r, z, 0.5f);
    r = fmaf(r, z, 1.0f);
    r = fmaf(r, z, 1.0f);
    return r * __int_as_float((__float_as_int(t) + (127 - 0x4B400000)) << 23);
}
static __device__ __forceinline__ void splitpack(float p0, float p1,
                                                 uint32_t& hi, uint32_t& lo) {
    float h0 = __bfloat162float(__float2bfloat16(p0));
    float h1 = __bfloat162float(__float2bfloat16(p1));
    hi = packbf(h0, h1);
    lo = packbf(p0 - h0, p1 - h1);
}

// ===== GEMM variant A (QKV): 256 thr, CTA 128x128, BK=32, 2 CTA/SM =====
#define BKC_A 32
#define NCH_A (Dk / BKC_A)      // 16
#define PCH_A 80
#define A_SA_HI 0
#define A_SA_LO 10240
#define A_SB_HI 20480
#define A_SB_LO 30720
#define A_STG_B 40960
#define GEMM_SMEM_A (2 * A_STG_B)   // 81920

static __device__ __forceinline__ void load_chunk_a(
    char* stage, const bf16* __restrict__ Ah, const bf16* __restrict__ Al,
    const bf16* __restrict__ Bh, const bf16* __restrict__ Bl, int k0)
{
    const int tid = threadIdx.x;
    uint32_t sbase = (uint32_t)__cvta_generic_to_shared(stage);
#pragma unroll
    for (int j = 0; j < 8; j++) {
        const int idx = tid + j * 256;
        if (idx < 1024) {
            const int sp = idx >> 9;
            const int w  = idx & 511;
            const int r  = w >> 2;
            const int c  = w & 3;
            cp_async16(sbase + (sp ? A_SA_LO : A_SA_HI) + r * PCH_A + c * 16,
                       (sp ? Al : Ah) + (size_t)r * Dk + k0 + c * 8);
        } else {
            const int t  = idx - 1024;
            const int sp = t >> 9;
            const int w  = t & 511;
            const int r  = w >> 2;
            const int c  = w & 3;
            cp_async16(sbase + (sp ? A_SB_LO : A_SB_HI) + r * PCH_A + c * 16,
                       (sp ? Bl : Bh) + (size_t)r * Dk + k0 + c * 8);
        }
    }
}

struct WAcc { float v[4][4][4]; };

static __device__ __forceinline__ void mma_mainloop_a(
    const bf16* __restrict__ Ahi, const bf16* __restrict__ Alo,
    const bf16* __restrict__ Bhi, const bf16* __restrict__ Blo,
    int m0, int n0, char* smem, WAcc& acc)
{
    const int tid   = threadIdx.x;
    const int wid   = tid >> 5;
    const int lane  = tid & 31;
    const int warpM = wid >> 2;
    const int warpN = wid & 3;
    const int lr    = lane & 7;
    const int lb3   = (lane >> 3) & 1;
    const int lb4   = (lane >> 4) & 1;

    const uint32_t abase = (uint32_t)((warpM * 64 + lr + lb3 * 8) * PCH_A + lb4 * 16);
    const uint32_t bbase = (uint32_t)((warpN * 32 + lr + lb4 * 8) * PCH_A + lb3 * 16);

    const bf16* Ah = Ahi + (size_t)m0 * Dk;
    const bf16* Al = Alo + (size_t)m0 * Dk;
    const bf16* Bh = Bhi + (size_t)n0 * Dk;
    const bf16* Bl = Blo + (size_t)n0 * Dk;

    uint32_t sbase = (uint32_t)__cvta_generic_to_shared(smem);

    load_chunk_a(smem, Ah, Al, Bh, Bl, 0);
    cp_commit();

    for (int c = 0; c < NCH_A; c++) {
        cp_wait<0>();
        __syncthreads();
        if (c + 1 < NCH_A) {
            load_chunk_a(smem + ((c + 1) & 1) * A_STG_B, Ah, Al, Bh, Bl, (c + 1) * BKC_A);
            cp_commit();
        }

        const uint32_t sg = sbase + (c & 1) * A_STG_B;
#pragma unroll
        for (int kh = 0; kh < 2; kh++) {
            uint32_t bh_[4][2], bl_[4][2];
#pragma unroll
            for (int nfp = 0; nfp < 2; nfp++) {
                const uint32_t bo = sg + bbase + nfp * (16 * PCH_A) + kh * 32;
                LDSM_X4(bh_[2 * nfp][0], bh_[2 * nfp][1],
                        bh_[2 * nfp + 1][0], bh_[2 * nfp + 1][1], bo + A_SB_HI);
                LDSM_X4(bl_[2 * nfp][0], bl_[2 * nfp][1],
                        bl_[2 * nfp + 1][0], bl_[2 * nfp + 1][1], bo + A_SB_LO);
            }
#pragma unroll
            for (int mf = 0; mf < 4; mf++) {
                const uint32_t ao = sg + abase + mf * (16 * PCH_A) + kh * 32;
                uint32_t ah[4], al[4];
                LDSM_X4(ah[0], ah[1], ah[2], ah[3], ao + A_SA_HI);
                LDSM_X4(al[0], al[1], al[2], al[3], ao + A_SA_LO);
#pragma unroll
                for (int nf = 0; nf < 4; nf++) MMA16816(acc.v[mf][nf], ah, bh_[nf]);
#pragma unroll
                for (int nf = 0; nf < 4; nf++) MMA16816(acc.v[mf][nf], ah, bl_[nf]);
#pragma unroll
                for (int nf = 0; nf < 4; nf++) MMA16816(acc.v[mf][nf], al, bh_[nf]);
            }
        }
    }
}

// ===== GEMM variant B (out): 512 thr, CTA 128x256, BK=64, 1 CTA/SM =====
#define BKC_B 64
#define NCH_B (Dk / BKC_B)      // 8
#define PCH_B 144
#define B_SA_HI 0
#define B_SA_LO 18432
#define B_SB_HI 36864
#define B_SB_LO 73728
#define B_STG_B 110592
#define GEMM_SMEM_B (2 * B_STG_B)   // 221184

static __device__ __forceinline__ void load_chunk_b(
    char* stage, const bf16* __restrict__ Ah, const bf16* __restrict__ Al,
    const bf16* __restrict__ Bh, const bf16* __restrict__ Bl, int k0)
{
    const int tid = threadIdx.x;
    uint32_t sbase = (uint32_t)__cvta_generic_to_shared(stage);
#pragma unroll
    for (int j = 0; j < 12; j++) {
        const int idx = tid + j * 512;
        if (idx < 2048) {
            const int sp = idx >> 10;
            const int w  = idx & 1023;
            const int r  = w >> 3;
            const int c  = w & 7;
            cp_async16(sbase + (sp ? B_SA_LO : B_SA_HI) + r * PCH_B + c * 16,
                       (sp ? Al : Ah) + (size_t)r * Dk + k0 + c * 8);
        } else {
            const int t  = idx - 2048;
            const int sp = t >> 11;
            const int w  = t & 2047;
            const int r  = w >> 3;
            const int c  = w & 7;
            cp_async16(sbase + (sp ? B_SB_LO : B_SB_HI) + r * PCH_B + c * 16,
                       (sp ? Bl : Bh) + (size_t)r * Dk + k0 + c * 8);
        }
    }
}

static __device__ __forceinline__ void mma_mainloop_b(
    const bf16* __restrict__ Ahi, const bf16* __restrict__ Alo,
    const bf16* __restrict__ Bhi, const bf16* __restrict__ Blo,
    int m0, int n0, char* smem, WAcc& acc)
{
    const int tid   = threadIdx.x;
    const int wid   = tid >> 5;
    const int lane  = tid & 31;
    const int warpM = wid >> 3;
    const int warpN = wid & 7;
    const int lr    = lane & 7;
    const int lb3   = (lane >> 3) & 1;
    const int lb4   = (lane >> 4) & 1;

    const uint32_t abase = (uint32_t)((warpM * 64 + lr + lb3 * 8) * PCH_B + lb4 * 16);
    const uint32_t bbase = (uint32_t)((warpN * 32 + lr + lb4 * 8) * PCH_B + lb3 * 16);

    const bf16* Ah = Ahi + (size_t)m0 * Dk;
    const bf16* Al = Alo + (size_t)m0 * Dk;
    const bf16* Bh = Bhi + (size_t)n0 * Dk;
    const bf16* Bl = Blo + (size_t)n0 * Dk;

    uint32_t sbase = (uint32_t)__cvta_generic_to_shared(smem);

    load_chunk_b(smem, Ah, Al, Bh, Bl, 0);
    cp_commit();

    for (int c = 0; c < NCH_B; c++) {
        cp_wait<0>();
        __syncthreads();
        if (c + 1 < NCH_B) {
            load_chunk_b(smem + ((c + 1) & 1) * B_STG_B, Ah, Al, Bh, Bl, (c + 1) * BKC_B);
            cp_commit();
        }

        const uint32_t sg = sbase + (c & 1) * B_STG_B;
#pragma unroll
        for (int kh = 0; kh < 4; kh++) {
            uint32_t bh_[4][2], bl_[4][2];
#pragma unroll
            for (int nfp = 0; nfp < 2; nfp++) {
                const uint32_t bo = sg + bbase + nfp * (16 * PCH_B) + kh * 32;
                LDSM_X4(bh_[2 * nfp][0], bh_[2 * nfp][1],
                        bh_[2 * nfp + 1][0], bh_[2 * nfp + 1][1], bo + B_SB_HI);
                LDSM_X4(bl_[2 * nfp][0], bl_[2 * nfp][1],
                        bl_[2 * nfp + 1][0], bl_[2 * nfp + 1][1], bo + B_SB_LO);
            }
#pragma unroll
            for (int mf = 0; mf < 4; mf++) {
                const uint32_t ao = sg + abase + mf * (16 * PCH_B) + kh * 32;
                uint32_t ah[4], al[4];
                LDSM_X4(ah[0], ah[1], ah[2], ah[3], ao + B_SA_HI);
                LDSM_X4(al[0], al[1], al[2], al[3], ao + B_SA_LO);
#pragma unroll
                for (int nf = 0; nf < 4; nf++) MMA16816(acc.v[mf][nf], ah, bh_[nf]);
#pragma unroll
                for (int nf = 0; nf < 4; nf++) MMA16816(acc.v[mf][nf], ah, bl_[nf]);
#pragma unroll
                for (int nf = 0; nf < 4; nf++) MMA16816(acc.v[mf][nf], al, bh_[nf]);
            }
        }
    }
}

// ---------------- QKV projection (variant A) ----------------
__global__ __launch_bounds__(256, 2)
void qkv_mma_kernel(const float* __restrict__ bq, const float* __restrict__ bk,
                    const float* __restrict__ bv)
{
    extern __shared__ char smem[];
    const int z  = blockIdx.z;
    const int m0 = blockIdx.y * 128;
    const int n0 = blockIdx.x * 128;

    WAcc acc;
#pragma unroll
    for (int a = 0; a < 4; a++)
#pragma unroll
        for (int b = 0; b < 4; b++)
#pragma unroll
            for (int cc = 0; cc < 4; cc++) acc.v[a][b][cc] = 0.f;

    mma_mainloop_a(g_xhi[z], g_xlo[z], g_whi[z], g_wlo[z], m0, n0, smem, acc);

    const float* bias = (z == 0) ? bq : (z == 1) ? bk : bv;
    bf16* oh = (z == 0) ? g_Qh : (z == 1) ? g_Kh : g_Vh;
    bf16* ol = (z == 0) ? g_Ql : (z == 1) ? g_Kl : g_Vl;

    const int lane  = threadIdx.x & 31;
    const int wid   = threadIdx.x >> 5;
    const int warpM = wid >> 2, warpN = wid & 3;
    const int g     = lane >> 2, q = lane & 3;

#pragma unroll
    for (int mf = 0; mf < 4; mf++) {
#pragma unroll
        for (int half = 0; half < 2; half++) {
            const int m  = m0 + warpM * 64 + mf * 16 + g + half * 8;
            const int bb = m / Sk;
            const int ss = m - bb * Sk;
#pragma unroll
            for (int nf = 0; nf < 4; nf++) {
                const int n  = n0 + warpN * 32 + nf * 8 + q * 2;
                const int hh = n >> 6;
                const int df = n & 63;
                float v0 = acc.v[mf][nf][half * 2 + 0] + bias[n];
                float v1 = acc.v[mf][nf][half * 2 + 1] + bias[n + 1];
                bf16 h0 = __float2bfloat16(v0);
                bf16 h1 = __float2bfloat16(v1);
                bf16 l0 = __float2bfloat16(v0 - __bfloat162float(h0));
                bf16 l1 = __float2bfloat16(v1 - __bfloat162float(h1));
                const size_t bh = (size_t)bb * Hk + hh;
                if (z < 2) {
                    const size_t o = (bh * Sk + ss) * DFk + df;
                    *(__nv_bfloat162*)&oh[o] = __halves2bfloat162(h0, h1);
                    *(__nv_bfloat162*)&ol[o] = __halves2bfloat162(l0, l1);
                } else {
                    const size_t o = (bh * DFk + df) * Sk + ss;
                    oh[o] = h0; oh[o + Sk] = h1;
                    ol[o] = l0; ol[o + Sk] = l1;
                }
            }
        }
    }
}

// ---------------- output projection (variant B) ----------------
__global__ __launch_bounds__(512, 1)
void out_mma_kernel(const float* __restrict__ bo, float* __restrict__ out)
{
    extern __shared__ char smem[];
    const int m0 = blockIdx.y * 128;
    const int n0 = blockIdx.x * 256;

    WAcc acc;
#pragma unroll
    for (int a = 0; a < 4; a++)
#pragma unroll
        for (int b = 0; b < 4; b++)
#pragma unroll
            for (int cc = 0; cc < 4; cc++) acc.v[a][b][cc] = 0.f;

    mma_mainloop_b(g_chi, g_clo, g_whi[3], g_wlo[3], m0, n0, smem, acc);

    const int lane  = threadIdx.x & 31;
    const int wid   = threadIdx.x >> 5;
    const int warpM = wid >> 3, warpN = wid & 7;
    const int g     = lane >> 2, q = lane & 3;

#pragma unroll
    for (int mf = 0; mf < 4; mf++) {
#pragma unroll
        for (int half = 0; half < 2; half++) {
            const int m = m0 + warpM * 64 + mf * 16 + g + half * 8;
#pragma unroll
            for (int nf = 0; nf < 4; nf++) {
                const int n = n0 + warpN * 32 + nf * 8 + q * 2;
                float2 v;
                v.x = acc.v[mf][nf][half * 2 + 0] + bo[n];
                v.y = acc.v[mf][nf][half * 2 + 1] + bo[n + 1];
                *(float2*)(out + (size_t)m * Dk + n) = v;
            }
        }
    }
}

// ---------------- fused fp32 -> bf16 hi/lo split ----------------
#define NX4 (ROWS * Dk / 4)
#define NW4 (Dk * Dk / 4)
#define CVT_TOT (3 * NX4 + 4 * NW4)

__global__ void cvt_all_kernel(const float* __restrict__ q, const float* __restrict__ k,
                               const float* __restrict__ v, const float* __restrict__ Wq,
                               const float* __restrict__ Wk, const float* __restrict__ Wv,
                               const float* __restrict__ Wo)
{
    const int i = blockIdx.x * blockDim.x + threadIdx.x;
    if (i >= CVT_TOT) return;
    const float* src;
    bf16 *hi, *lo;
    int off;
    if (i < 3 * NX4) {
        const int which = i / NX4;
        off = i - which * NX4;
        src = (which == 0) ? q : (which == 1) ? k : v;
        hi = g_xhi[which]; lo = g_xlo[which];
    } else {
        const int j = i - 3 * NX4;
        const int which = j / NW4;
        off = j - which * NW4;
        src = (which == 0) ? Wq : (which == 1) ? Wk : (which == 2) ? Wv : Wo;
        hi = g_whi[which]; lo = g_wlo[which];
    }
    float4 x = ((const float4*)src)[off];
    bf16 h0 = __float2bfloat16(x.x), h1 = __float2bfloat16(x.y);
    bf16 h2 = __float2bfloat16(x.z), h3 = __float2bfloat16(x.w);
    bf16 l0 = __float2bfloat16(x.x - __bfloat162float(h0));
    bf16 l1 = __float2bfloat16(x.y - __bfloat162float(h1));
    bf16 l2 = __float2bfloat16(x.z - __bfloat162float(h2));
    bf16 l3 = __float2bfloat16(x.w - __bfloat162float(h3));
    ((__nv_bfloat162*)hi)[2 * off]     = __halves2bfloat162(h0, h1);
    ((__nv_bfloat162*)hi)[2 * off + 1] = __halves2bfloat162(h2, h3);
    ((__nv_bfloat162*)lo)[2 * off]     = __halves2bfloat162(l0, l1);
    ((__nv_bfloat162*)lo)[2 * off + 1] = __halves2bfloat162(l2, l3);
}

// ------ balanced streaming tensor-core attention (unchanged from R13) ----------
#define SKH 0
#define SKL 14400
#define SVH 28800
#define SVL 42624
#define ATTN_SMEM 112896

__global__ __launch_bounds__(256, 2)
void attn_mma_kernel()
{
    extern __shared__ bf16 smb[];
    const int bh  = blockIdx.x;
    const int tid = threadIdx.x;
    uint32_t sb = (uint32_t)__cvta_generic_to_shared(smb);

    for (int u = tid; u < 2 * Sk * 8; u += 256) {
        int sp = (u >= Sk * 8), w2 = u - sp * Sk * 8, r = w2 >> 3, c = w2 & 7;
        cp_async16(sb + (uint32_t)((sp ? SKL : SKH) + r * 72 + c * 8) * 2,
                   (sp ? g_Kl : g_Kh) + ((size_t)bh * Sk + r) * DFk + c * 8);
    }
    for (int u = tid; u < 2 * 64 * 26; u += 256) {
        int sp = (u >= 64 * 26), w2 = u - sp * 64 * 26, r = w2 / 26, c = w2 - r * 26;
        int cc = min(c, 24);
        cp_async16(sb + (uint32_t)((sp ? SVL : SVH) + r * 216 + c * 8) * 2,
                   (sp ? g_Vl : g_Vh) + ((size_t)bh * DFk + r) * Sk + cc * 8);
    }
    cp_commit();

    const int w = tid >> 5, lane = tid & 31, g = lane >> 2, q = lane & 3;
    const int bbb = bh >> 3, hh = bh & 7;

    cp_wait<0>();
    __syncthreads();

    const int nb = (w >= 3) ? 2 : 1;
    for (int bi = 0; bi < nb; bi++) {
        const int blk = bi ? (w - 3) : (12 - w);
        const int qr0 = blk * 16 + g;
        const int qr1 = qr0 + 8;
        const int KCW = blk + 1;

        uint32_t qah[4][4], qal[4][4];
        {
            const int r1c = min(qr1, Sk - 1);
            const bf16* Qh0 = g_Qh + ((size_t)bh * Sk + qr0) * DFk;
            const bf16* Qh1 = g_Qh + ((size_t)bh * Sk + r1c) * DFk;
            const bf16* Ql0 = g_Ql + ((size_t)bh * Sk + qr0) * DFk;
            const bf16* Ql1 = g_Ql + ((size_t)bh * Sk + r1c) * DFk;
#pragma unroll
            for (int kc = 0; kc < 4; kc++) {
                const int col = 16 * kc + 2 * q;
                qah[kc][0] = *(const uint32_t*)(Qh0 + col);
                qah[kc][1] = *(const uint32_t*)(Qh1 + col);
                qah[kc][2] = *(const uint32_t*)(Qh0 + col + 8);
                qah[kc][3] = *(const uint32_t*)(Qh1 + col + 8);
                qal[kc][0] = *(const uint32_t*)(Ql0 + col);
                qal[kc][1] = *(const uint32_t*)(Ql1 + col);
                qal[kc][2] = *(const uint32_t*)(Ql0 + col + 8);
                qal[kc][3] = *(const uint32_t*)(Ql1 + col + 8);
            }
        }

        float oa[8][4];
#pragma unroll
        for (int nv = 0; nv < 8; nv++)
            oa[nv][0] = oa[nv][1] = oa[nv][2] = oa[nv][3] = 0.f;
        float sum0 = 0.f, sum1 = 0.f;

        for (int kc = 0; kc < KCW; kc++) {
            const bool d1 = (16 * kc + 8 < Sk);
            float s0[4] = {0.f, 0.f, 0.f, 0.f};
            float s1[4] = {0.f, 0.f, 0.f, 0.f};
#pragma unroll
            for (int dfc = 0; dfc < 4; dfc++) {
                const int o0 = (16 * kc + g) * 72 + 16 * dfc + 2 * q;
                uint32_t kb0[2], kl0[2], kb1[2], kl1[2];
                kb0[0] = *(const uint32_t*)&smb[SKH + o0];
                kb0[1] = *(const uint32_t*)&smb[SKH + o0 + 8];
                kl0[0] = *(const uint32_t*)&smb[SKL + o0];
                kl0[1] = *(const uint32_t*)&smb[SKL + o0 + 8];
                if (d1) {
                    const int o1 = o0 + 8 * 72;
                    kb1[0] = *(const uint32_t*)&smb[SKH + o1];
                    kb1[1] = *(const uint32_t*)&smb[SKH + o1 + 8];
                    kl1[0] = *(const uint32_t*)&smb[SKL + o1];
                    kl1[1] = *(const uint32_t*)&smb[SKL + o1 + 8];
                }
                MMA16816(s0, qah[dfc], kb0);
                if (d1) MMA16816(s1, qah[dfc], kb1);
                MMA16816(s0, qah[dfc], kl0);
                if (d1) MMA16816(s1, qah[dfc], kl1);
                MMA16816(s0, qal[dfc], kb0);
                if (d1) MMA16816(s1, qal[dfc], kb1);
            }
            const int k0 = 16 * kc + 2 * q;
            s0[0] = fast_exp((k0     <= qr0) ? s0[0] * SCALE : -1e30f);
            s0[1] = fast_exp((k0 + 1 <= qr0) ? s0[1] * SCALE : -1e30f);
            s0[2] = fast_exp((k0     <= qr1) ? s0[2] * SCALE : -1e30f);
            s0[3] = fast_exp((k0 + 1 <= qr1) ? s0[3] * SCALE : -1e30f);
            sum0 += s0[0] + s0[1];
            sum1 += s0[2] + s0[3];
            if (d1) {
                const int k1 = k0 + 8;
                s1[0] = fast_exp((k1     <= qr0) ? s1[0] * SCALE : -1e30f);
                s1[1] = fast_exp((k1 + 1 <= qr0) ? s1[1] * SCALE : -1e30f);
                s1[2] = fast_exp((k1     <= qr1) ? s1[2] * SCALE : -1e30f);
                s1[3] = fast_exp((k1 + 1 <= qr1) ? s1[3] * SCALE : -1e30f);
                sum0 += s1[0] + s1[1];
                sum1 += s1[2] + s1[3];
            }
            uint32_t ph[4], pl[4];
            splitpack(s0[0], s0[1], ph[0], pl[0]);
            splitpack(s0[2], s0[3], ph[1], pl[1]);
            if (d1) {
                splitpack(s1[0], s1[1], ph[2], pl[2]);
                splitpack(s1[2], s1[3], ph[3], pl[3]);
            } else {
                ph[2] = ph[3] = pl[2] = pl[3] = 0u;
            }
#pragma unroll
            for (int nvp = 0; nvp < 4; nvp++) {
                const int nv0 = 2 * nvp, nv1 = nv0 + 1;
                const int o0 = (8 * nv0 + g) * 216 + 16 * kc + 2 * q;
                const int o1 = o0 + 8 * 216;
                uint32_t vb0[2], vl0[2], vb1[2], vl1[2];
                vb0[0] = *(const uint32_t*)&smb[SVH + o0];
                vb0[1] = *(const uint32_t*)&smb[SVH + o0 + 8];
                vl0[0] = *(const uint32_t*)&smb[SVL + o0];
                vl0[1] = *(const uint32_t*)&smb[SVL + o0 + 8];
                vb1[0] = *(const uint32_t*)&smb[SVH + o1];
                vb1[1] = *(const uint32_t*)&smb[SVH + o1 + 8];
                vl1[0] = *(const uint32_t*)&smb[SVL + o1];
                vl1[1] = *(const uint32_t*)&smb[SVL + o1 + 8];
                MMA16816(oa[nv0], ph, vb0);
                MMA16816(oa[nv1], ph, vb1);
                MMA16816(oa[nv0], ph, vl0);
                MMA16816(oa[nv1], ph, vl1);
                MMA16816(oa[nv0], pl, vb0);
                MMA16816(oa[nv1], pl, vb1);
            }
        }

        sum0 += __shfl_xor_sync(0xFFFFFFFFu, sum0, 1);
        sum0 += __shfl_xor_sync(0xFFFFFFFFu, sum0, 2);
        sum1 += __shfl_xor_sync(0xFFFFFFFFu, sum1, 1);
        sum1 += __shfl_xor_sync(0xFFFFFFFFu, sum1, 2);
        const float inv0 = (qr0 == 0) ? 0.f : 1.f / fmaxf(sum0, 1e-37f);
        const float inv1 = 1.f / fmaxf(sum1, 1e-37f);

#pragma unroll
        for (int nv = 0; nv < 8; nv++) {
            const int df = 8 * nv + 2 * q;
            {
                const float x0 = oa[nv][0] * inv0, x1 = oa[nv][1] * inv0;
                const size_t o = ((size_t)bbb * Sk + qr0) * Dk + hh * 64 + df;
                bf16 a = __float2bfloat16(x0);
                bf16 b = __float2bfloat16(x1);
                *(__nv_bfloat162*)&g_chi[o] = __halves2bfloat162(a, b);
                *(__nv_bfloat162*)&g_clo[o] = __halves2bfloat162(
                    __float2bfloat16(x0 - __bfloat162float(a)),
                    __float2bfloat16(x1 - __bfloat162float(b)));
            }
            if (qr1 < Sk) {
                const float x0 = oa[nv][2] * inv1, x1 = oa[nv][3] * inv1;
                const size_t o = ((size_t)bbb * Sk + qr1) * Dk + hh * 64 + df;
                bf16 a = __float2bfloat16(x0);
                bf16 b = __float2bfloat16(x1);
                *(__nv_bfloat162*)&g_chi[o] = __halves2bfloat162(a, b);
                *(__nv_bfloat162*)&g_clo[o] = __halves2bfloat162(
                    __float2bfloat16(x0 - __bfloat162float(a)),
                    __float2bfloat16(x1 - __bfloat162float(b)));
            }
        }
    }
}

// ---------------- launch ----------------
extern "C" void kernel_launch(void* const* d_in, const int* in_sizes, int n_in,
                              void* d_out, int out_size)
{
    const float* q  = (const float*)d_in[0];
    const float* k  = (const float*)d_in[1];
    const float* v  = (const float*)d_in[2];
    const float* Wq = (const float*)d_in[3];
    const float* bq = (const float*)d_in[4];
    const float* Wk = (const float*)d_in[5];
    const float* bk = (const float*)d_in[6];
    const float* Wv = (const float*)d_in[7];
    const float* bv = (const float*)d_in[8];
    const float* Wo = (const float*)d_in[9];
    const float* bo = (const float*)d_in[10];
    float* out = (float*)d_out;

    cvt_all_kernel<<<(CVT_TOT + 255) / 256, 256>>>(q, k, v, Wq, Wk, Wv, Wo);

    cudaFuncSetAttribute(qkv_mma_kernel, cudaFuncAttributeMaxDynamicSharedMemorySize,
                         GEMM_SMEM_A);
    qkv_mma_kernel<<<dim3(Dk / 128, ROWS / 128, 3), 256, GEMM_SMEM_A>>>(bq, bk, bv);

    cudaFuncSetAttribute(attn_mma_kernel, cudaFuncAttributeMaxDynamicSharedMemorySize,
                         ATTN_SMEM);
    attn_mma_kernel<<<Bk * Hk, 256, ATTN_SMEM>>>();

    cudaFuncSetAttribute(out_mma_kernel, cudaFuncAttributeMaxDynamicSharedMemorySize,
                         GEMM_SMEM_B);
    out_mma_kernel<<<dim3(Dk / 256, ROWS / 128, 1), 512, GEMM_SMEM_B>>>(bo, out);
}

// round 17
// speedup vs baseline: 1.1839x; 1.0506x over previous
#include <cuda_runtime.h>
#include <cuda_bf16.h>
#include <math.h>
#include <stdint.h>

#define Bk 128
#define Sk 200
#define Dk 512
#define Hk 8
#define DFk 64
#define ROWS (Bk * Sk)          // 25600
#define SCALE 0.125f

typedef __nv_bfloat16 bf16;

// ---------------- device scratch ----------------
__device__ __align__(256) bf16 g_whi[4][(size_t)Dk * Dk];
__device__ __align__(256) bf16 g_wlo[4][(size_t)Dk * Dk];
__device__ __align__(256) bf16 g_Qh[(size_t)ROWS * Dk];   // [bh][s][64]
__device__ __align__(256) bf16 g_Ql[(size_t)ROWS * Dk];
__device__ __align__(256) bf16 g_Kh[(size_t)ROWS * Dk];
__device__ __align__(256) bf16 g_Kl[(size_t)ROWS * Dk];
__device__ __align__(256) bf16 g_Vh[(size_t)ROWS * Dk];   // [bh][df][s]
__device__ __align__(256) bf16 g_Vl[(size_t)ROWS * Dk];
__device__ __align__(256) bf16 g_chi[(size_t)ROWS * Dk];
__device__ __align__(256) bf16 g_clo[(size_t)ROWS * Dk];

// ---------------- helpers ----------------
#define MMA16816(d, a, b)                                                      \
    asm("mma.sync.aligned.m16n8k16.row.col.f32.bf16.bf16.f32 "                 \
        "{%0,%1,%2,%3}, {%4,%5,%6,%7}, {%8,%9}, {%0,%1,%2,%3};"                \
        : "+f"((d)[0]), "+f"((d)[1]), "+f"((d)[2]), "+f"((d)[3])               \
        : "r"((a)[0]), "r"((a)[1]), "r"((a)[2]), "r"((a)[3]),                  \
          "r"((b)[0]), "r"((b)[1]))

#define LDSM_X4(r0, r1, r2, r3, addr)                                          \
    asm volatile("ldmatrix.sync.aligned.m8n8.x4.shared.b16 {%0,%1,%2,%3}, [%4];" \
                 : "=r"(r0), "=r"(r1), "=r"(r2), "=r"(r3) : "r"(addr))

static __device__ __forceinline__ void cp_async16(uint32_t saddr, const void* gaddr) {
    asm volatile("cp.async.cg.shared.global [%0], [%1], 16;"
                 :: "r"(saddr), "l"(gaddr));
}
static __device__ __forceinline__ void cp_commit() {
    asm volatile("cp.async.commit_group;" ::: "memory");
}
template <int N>
static __device__ __forceinline__ void cp_wait() {
    asm volatile("cp.async.wait_group %0;" :: "n"(N) : "memory");
}
static __device__ __forceinline__ uint32_t packbf(float lo, float hi) {
    uint32_t r;
    asm("cvt.rn.bf16x2.f32 %0, %1, %2;" : "=r"(r) : "f"(hi), "f"(lo));
    return r;
}
static __device__ __forceinline__ float fast_exp(float x) {
    x = fmaxf(x, -87.0f);
    float t = fmaf(x, 1.4426950408889634f, 12582912.0f);
    float f = fmaf(x, 1.4426950408889634f, -(t - 12582912.0f));
    float z = f * 0.6931471805599453f;
    float r = fmaf(0.0013888889f, z, 0.0083333333f);
    r = fmaf(r, z, 0.041666667f);
    r = fmaf(r, z, 0.16666667f);
    r = fmaf(r, z, 0.5f);
    r = fmaf(r, z, 1.0f);
    r = fmaf(r, z, 1.0f);
    return r * __int_as_float((__float_as_int(t) + (127 - 0x4B400000)) << 23);
}
static __device__ __forceinline__ void splitpack(float p0, float p1,
                                                 uint32_t& hi, uint32_t& lo) {
    float h0 = __bfloat162float(__float2bfloat16(p0));
    float h1 = __bfloat162float(__float2bfloat16(p1));
    hi = packbf(h0, h1);
    lo = packbf(p0 - h0, p1 - h1);
}
// 8 fp32 -> packed hi/lo bf16 (identical math to the old cvt kernel)
static __device__ __forceinline__ void cvt8(const float* f, uint4& H, uint4& L) {
    uint32_t* Hp = (uint32_t*)&H;
    uint32_t* Lp = (uint32_t*)&L;
#pragma unroll
    for (int i = 0; i < 4; i++) {
        bf16 h0 = __float2bfloat16(f[2 * i]);
        bf16 h1 = __float2bfloat16(f[2 * i + 1]);
        bf16 l0 = __float2bfloat16(f[2 * i]     - __bfloat162float(h0));
        bf16 l1 = __float2bfloat16(f[2 * i + 1] - __bfloat162float(h1));
        __nv_bfloat162 hh = __halves2bfloat162(h0, h1);
        __nv_bfloat162 ll = __halves2bfloat162(l0, l1);
        Hp[i] = *(uint32_t*)&hh;
        Lp[i] = *(uint32_t*)&ll;
    }
}

// ===== GEMM variant A (QKV): 256 thr, CTA 128x128, BK=32, 2 CTA/SM,
//       fused fp32->hi/lo conversion on the A path =====
#define BKC_A 32
#define NCH_A (Dk / BKC_A)      // 16
#define PCH_A 80
#define A_SA_HI 0
#define A_SA_LO 10240
#define A_SB_HI 20480
#define A_SB_LO 30720
#define A_STG_B 40960
#define GEMM_SMEM_A (2 * A_STG_B)   // 81920

static __device__ __forceinline__ void load_b_a(
    char* stage, const bf16* __restrict__ Bh, const bf16* __restrict__ Bl, int k0)
{
    const int tid = threadIdx.x;
    uint32_t sbase = (uint32_t)__cvta_generic_to_shared(stage);
#pragma unroll
    for (int j = 0; j < 4; j++) {
        const int idx = tid + j * 256;     // 0..1023
        const int sp = idx >> 9;
        const int w  = idx & 511;
        const int r  = w >> 2;
        const int c  = w & 3;
        cp_async16(sbase + (sp ? A_SB_LO : A_SB_HI) + r * PCH_A + c * 16,
                   (sp ? Bl : Bh) + (size_t)r * Dk + k0 + c * 8);
    }
}
// LDG fp32 A groups for a chunk: 512 groups of 8 floats; 2 per thread.
static __device__ __forceinline__ void ldg_a(float* v, const float* __restrict__ X,
                                             int k0)
{
    const int tid = threadIdx.x;
#pragma unroll
    for (int t = 0; t < 2; t++) {
        const int gi = tid + t * 256;
        const int r  = gi >> 2;
        const int c  = gi & 3;
        const float4* p = (const float4*)(X + (size_t)r * Dk + k0 + c * 8);
        *(float4*)(v + t * 8)     = p[0];
        *(float4*)(v + t * 8 + 4) = p[1];
    }
}
static __device__ __forceinline__ void sts_a(char* stage, const float* v)
{
    const int tid = threadIdx.x;
#pragma unroll
    for (int t = 0; t < 2; t++) {
        const int gi = tid + t * 256;
        const int r  = gi >> 2;
        const int c  = gi & 3;
        uint4 H, L;
        cvt8(v + t * 8, H, L);
        *(uint4*)(stage + A_SA_HI + r * PCH_A + c * 16) = H;
        *(uint4*)(stage + A_SA_LO + r * PCH_A + c * 16) = L;
    }
}

struct WAcc { float v[4][4][4]; };

static __device__ __forceinline__ void mma_mainloop_af(
    const float* __restrict__ X,
    const bf16* __restrict__ Bhi, const bf16* __restrict__ Blo,
    int m0, int n0, char* smem, WAcc& acc)
{
    const int tid   = threadIdx.x;
    const int wid   = tid >> 5;
    const int lane  = tid & 31;
    const int warpM = wid >> 2;
    const int warpN = wid & 3;
    const int lr    = lane & 7;
    const int lb3   = (lane >> 3) & 1;
    const int lb4   = (lane >> 4) & 1;

    const uint32_t abase = (uint32_t)((warpM * 64 + lr + lb3 * 8) * PCH_A + lb4 * 16);
    const uint32_t bbase = (uint32_t)((warpN * 32 + lr + lb4 * 8) * PCH_A + lb3 * 16);

    const float* Xa = X + (size_t)m0 * Dk;
    const bf16* Bh = Bhi + (size_t)n0 * Dk;
    const bf16* Bl = Blo + (size_t)n0 * Dk;

    uint32_t sbase = (uint32_t)__cvta_generic_to_shared(smem);

    // prologue: chunk 0 (A sync-converted, B async)
    {
        float v[16];
        ldg_a(v, Xa, 0);
        sts_a(smem, v);
        load_b_a(smem, Bh, Bl, 0);
        cp_commit();
    }

    for (int c = 0; c < NCH_A; c++) {
        cp_wait<0>();
        __syncthreads();

        float nxt[16];
        const bool havn = (c + 1 < NCH_A);
        char* nstage = smem + ((c + 1) & 1) * A_STG_B;
        if (havn) {
            ldg_a(nxt, Xa, (c + 1) * BKC_A);           // LDGs issue early
            load_b_a(nstage, Bh, Bl, (c + 1) * BKC_A);
            cp_commit();
        }

        const uint32_t sg = sbase + (c & 1) * A_STG_B;
#pragma unroll
        for (int kh = 0; kh < 2; kh++) {
            uint32_t bh_[4][2], bl_[4][2];
#pragma unroll
            for (int nfp = 0; nfp < 2; nfp++) {
                const uint32_t bo = sg + bbase + nfp * (16 * PCH_A) + kh * 32;
                LDSM_X4(bh_[2 * nfp][0], bh_[2 * nfp][1],
                        bh_[2 * nfp + 1][0], bh_[2 * nfp + 1][1], bo + A_SB_HI);
                LDSM_X4(bl_[2 * nfp][0], bl_[2 * nfp][1],
                        bl_[2 * nfp + 1][0], bl_[2 * nfp + 1][1], bo + A_SB_LO);
            }
#pragma unroll
            for (int mf = 0; mf < 4; mf++) {
                const uint32_t ao = sg + abase + mf * (16 * PCH_A) + kh * 32;
                uint32_t ah[4], al[4];
                LDSM_X4(ah[0], ah[1], ah[2], ah[3], ao + A_SA_HI);
                LDSM_X4(al[0], al[1], al[2], al[3], ao + A_SA_LO);
#pragma unroll
                for (int nf = 0; nf < 4; nf++) MMA16816(acc.v[mf][nf], ah, bh_[nf]);
#pragma unroll
                for (int nf = 0; nf < 4; nf++) MMA16816(acc.v[mf][nf], ah, bl_[nf]);
#pragma unroll
                for (int nf = 0; nf < 4; nf++) MMA16816(acc.v[mf][nf], al, bh_[nf]);
            }
        }
        if (havn) sts_a(nstage, nxt);                  // STS after MMAs
    }
}

// ===== GEMM variant B (out): 512 thr, CTA 128x256, BK=64, 1 CTA/SM =====
#define BKC_B 64
#define NCH_B (Dk / BKC_B)      // 8
#define PCH_B 144
#define B_SA_HI 0
#define B_SA_LO 18432
#define B_SB_HI 36864
#define B_SB_LO 73728
#define B_STG_B 110592
#define GEMM_SMEM_B (2 * B_STG_B)   // 221184

static __device__ __forceinline__ void load_chunk_b(
    char* stage, const bf16* __restrict__ Ah, const bf16* __restrict__ Al,
    const bf16* __restrict__ Bh, const bf16* __restrict__ Bl, int k0)
{
    const int tid = threadIdx.x;
    uint32_t sbase = (uint32_t)__cvta_generic_to_shared(stage);
#pragma unroll
    for (int j = 0; j < 12; j++) {
        const int idx = tid + j * 512;
        if (idx < 2048) {
            const int sp = idx >> 10;
            const int w  = idx & 1023;
            const int r  = w >> 3;
            const int c  = w & 7;
            cp_async16(sbase + (sp ? B_SA_LO : B_SA_HI) + r * PCH_B + c * 16,
                       (sp ? Al : Ah) + (size_t)r * Dk + k0 + c * 8);
        } else {
            const int t  = idx - 2048;
            const int sp = t >> 11;
            const int w  = t & 2047;
            const int r  = w >> 3;
            const int c  = w & 7;
            cp_async16(sbase + (sp ? B_SB_LO : B_SB_HI) + r * PCH_B + c * 16,
                       (sp ? Bl : Bh) + (size_t)r * Dk + k0 + c * 8);
        }
    }
}

static __device__ __forceinline__ void mma_mainloop_b(
    const bf16* __restrict__ Ahi, const bf16* __restrict__ Alo,
    const bf16* __restrict__ Bhi, const bf16* __restrict__ Blo,
    int m0, int n0, char* smem, WAcc& acc)
{
    const int tid   = threadIdx.x;
    const int wid   = tid >> 5;
    const int lane  = tid & 31;
    const int warpM = wid >> 3;
    const int warpN = wid & 7;
    const int lr    = lane & 7;
    const int lb3   = (lane >> 3) & 1;
    const int lb4   = (lane >> 4) & 1;

    const uint32_t abase = (uint32_t)((warpM * 64 + lr + lb3 * 8) * PCH_B + lb4 * 16);
    const uint32_t bbase = (uint32_t)((warpN * 32 + lr + lb4 * 8) * PCH_B + lb3 * 16);

    const bf16* Ah = Ahi + (size_t)m0 * Dk;
    const bf16* Al = Alo + (size_t)m0 * Dk;
    const bf16* Bh = Bhi + (size_t)n0 * Dk;
    const bf16* Bl = Blo + (size_t)n0 * Dk;

    uint32_t sbase = (uint32_t)__cvta_generic_to_shared(smem);

    load_chunk_b(smem, Ah, Al, Bh, Bl, 0);
    cp_commit();

    for (int c = 0; c < NCH_B; c++) {
        cp_wait<0>();
        __syncthreads();
        if (c + 1 < NCH_B) {
            load_chunk_b(smem + ((c + 1) & 1) * B_STG_B, Ah, Al, Bh, Bl, (c + 1) * BKC_B);
            cp_commit();
        }

        const uint32_t sg = sbase + (c & 1) * B_STG_B;
#pragma unroll
        for (int kh = 0; kh < 4; kh++) {
            uint32_t bh_[4][2], bl_[4][2];
#pragma unroll
            for (int nfp = 0; nfp < 2; nfp++) {
                const uint32_t bo = sg + bbase + nfp * (16 * PCH_B) + kh * 32;
                LDSM_X4(bh_[2 * nfp][0], bh_[2 * nfp][1],
                        bh_[2 * nfp + 1][0], bh_[2 * nfp + 1][1], bo + B_SB_HI);
                LDSM_X4(bl_[2 * nfp][0], bl_[2 * nfp][1],
                        bl_[2 * nfp + 1][0], bl_[2 * nfp + 1][1], bo + B_SB_LO);
            }
#pragma unroll
            for (int mf = 0; mf < 4; mf++) {
                const uint32_t ao = sg + abase + mf * (16 * PCH_B) + kh * 32;
                uint32_t ah[4], al[4];
                LDSM_X4(ah[0], ah[1], ah[2], ah[3], ao + B_SA_HI);
                LDSM_X4(al[0], al[1], al[2], al[3], ao + B_SA_LO);
#pragma unroll
                for (int nf = 0; nf < 4; nf++) MMA16816(acc.v[mf][nf], ah, bh_[nf]);
#pragma unroll
                for (int nf = 0; nf < 4; nf++) MMA16816(acc.v[mf][nf], ah, bl_[nf]);
#pragma unroll
                for (int nf = 0; nf < 4; nf++) MMA16816(acc.v[mf][nf], al, bh_[nf]);
            }
        }
    }
}

// ---------------- QKV projection (fused-cvt variant A) ----------------
__global__ __launch_bounds__(256, 2)
void qkv_mma_kernel(const float* __restrict__ q, const float* __restrict__ k,
                    const float* __restrict__ v,
                    const float* __restrict__ bq, const float* __restrict__ bk,
                    const float* __restrict__ bv)
{
    extern __shared__ char smem[];
    const int z  = blockIdx.z;
    const int m0 = blockIdx.y * 128;
    const int n0 = blockIdx.x * 128;

    const float* X = (z == 0) ? q : (z == 1) ? k : v;

    WAcc acc;
#pragma unroll
    for (int a = 0; a < 4; a++)
#pragma unroll
        for (int b = 0; b < 4; b++)
#pragma unroll
            for (int cc = 0; cc < 4; cc++) acc.v[a][b][cc] = 0.f;

    mma_mainloop_af(X, g_whi[z], g_wlo[z], m0, n0, smem, acc);

    const float* bias = (z == 0) ? bq : (z == 1) ? bk : bv;
    bf16* oh = (z == 0) ? g_Qh : (z == 1) ? g_Kh : g_Vh;
    bf16* ol = (z == 0) ? g_Ql : (z == 1) ? g_Kl : g_Vl;

    const int lane  = threadIdx.x & 31;
    const int wid   = threadIdx.x >> 5;
    const int warpM = wid >> 2, warpN = wid & 3;
    const int g     = lane >> 2, q4 = lane & 3;

#pragma unroll
    for (int mf = 0; mf < 4; mf++) {
#pragma unroll
        for (int half = 0; half < 2; half++) {
            const int m  = m0 + warpM * 64 + mf * 16 + g + half * 8;
            const int bb = m / Sk;
            const int ss = m - bb * Sk;
#pragma unroll
            for (int nf = 0; nf < 4; nf++) {
                const int n  = n0 + warpN * 32 + nf * 8 + q4 * 2;
                const int hh = n >> 6;
                const int df = n & 63;
                float v0 = acc.v[mf][nf][half * 2 + 0] + bias[n];
                float v1 = acc.v[mf][nf][half * 2 + 1] + bias[n + 1];
                bf16 h0 = __float2bfloat16(v0);
                bf16 h1 = __float2bfloat16(v1);
                bf16 l0 = __float2bfloat16(v0 - __bfloat162float(h0));
                bf16 l1 = __float2bfloat16(v1 - __bfloat162float(h1));
                const size_t bh = (size_t)bb * Hk + hh;
                if (z < 2) {
                    const size_t o = (bh * Sk + ss) * DFk + df;
                    *(__nv_bfloat162*)&oh[o] = __halves2bfloat162(h0, h1);
                    *(__nv_bfloat162*)&ol[o] = __halves2bfloat162(l0, l1);
                } else {
                    const size_t o = (bh * DFk + df) * Sk + ss;
                    oh[o] = h0; oh[o + Sk] = h1;
                    ol[o] = l0; ol[o + Sk] = l1;
                }
            }
        }
    }
}

// ---------------- output projection (variant B) ----------------
__global__ __launch_bounds__(512, 1)
void out_mma_kernel(const float* __restrict__ bo, float* __restrict__ out)
{
    extern __shared__ char smem[];
    const int m0 = blockIdx.y * 128;
    const int n0 = blockIdx.x * 256;

    WAcc acc;
#pragma unroll
    for (int a = 0; a < 4; a++)
#pragma unroll
        for (int b = 0; b < 4; b++)
#pragma unroll
            for (int cc = 0; cc < 4; cc++) acc.v[a][b][cc] = 0.f;

    mma_mainloop_b(g_chi, g_clo, g_whi[3], g_wlo[3], m0, n0, smem, acc);

    const int lane  = threadIdx.x & 31;
    const int wid   = threadIdx.x >> 5;
    const int warpM = wid >> 3, warpN = wid & 7;
    const int g     = lane >> 2, q = lane & 3;

#pragma unroll
    for (int mf = 0; mf < 4; mf++) {
#pragma unroll
        for (int half = 0; half < 2; half++) {
            const int m = m0 + warpM * 64 + mf * 16 + g + half * 8;
#pragma unroll
            for (int nf = 0; nf < 4; nf++) {
                const int n = n0 + warpN * 32 + nf * 8 + q * 2;
                float2 v;
                v.x = acc.v[mf][nf][half * 2 + 0] + bo[n];
                v.y = acc.v[mf][nf][half * 2 + 1] + bo[n + 1];
                *(float2*)(out + (size_t)m * Dk + n) = v;
            }
        }
    }
}

// ---------------- weights fp32 -> bf16 hi/lo split ----------------
#define NW4 (Dk * Dk / 4)
#define CVTW_TOT (4 * NW4)

__global__ void cvt_w_kernel(const float* __restrict__ Wq, const float* __restrict__ Wk,
                             const float* __restrict__ Wv, const float* __restrict__ Wo)
{
    const int i = blockIdx.x * blockDim.x + threadIdx.x;
    if (i >= CVTW_TOT) return;
    const int which = i / NW4;
    const int off   = i - which * NW4;
    const float* src = (which == 0) ? Wq : (which == 1) ? Wk : (which == 2) ? Wv : Wo;
    bf16* hi = g_whi[which];
    bf16* lo = g_wlo[which];
    float4 x = ((const float4*)src)[off];
    bf16 h0 = __float2bfloat16(x.x), h1 = __float2bfloat16(x.y);
    bf16 h2 = __float2bfloat16(x.z), h3 = __float2bfloat16(x.w);
    bf16 l0 = __float2bfloat16(x.x - __bfloat162float(h0));
    bf16 l1 = __float2bfloat16(x.y - __bfloat162float(h1));
    bf16 l2 = __float2bfloat16(x.z - __bfloat162float(h2));
    bf16 l3 = __float2bfloat16(x.w - __bfloat162float(h3));
    ((__nv_bfloat162*)hi)[2 * off]     = __halves2bfloat162(h0, h1);
    ((__nv_bfloat162*)hi)[2 * off + 1] = __halves2bfloat162(h2, h3);
    ((__nv_bfloat162*)lo)[2 * off]     = __halves2bfloat162(l0, l1);
    ((__nv_bfloat162*)lo)[2 * off + 1] = __halves2bfloat162(l2, l3);
}

// ------ balanced streaming tensor-core attention (unchanged from R13) ----------
#define SKH 0
#define SKL 14400
#define SVH 28800
#define SVL 42624
#define ATTN_SMEM 112896

__global__ __launch_bounds__(256, 2)
void attn_mma_kernel()
{
    extern __shared__ bf16 smb[];
    const int bh  = blockIdx.x;
    const int tid = threadIdx.x;
    uint32_t sb = (uint32_t)__cvta_generic_to_shared(smb);

    for (int u = tid; u < 2 * Sk * 8; u += 256) {
        int sp = (u >= Sk * 8), w2 = u - sp * Sk * 8, r = w2 >> 3, c = w2 & 7;
        cp_async16(sb + (uint32_t)((sp ? SKL : SKH) + r * 72 + c * 8) * 2,
                   (sp ? g_Kl : g_Kh) + ((size_t)bh * Sk + r) * DFk + c * 8);
    }
    for (int u = tid; u < 2 * 64 * 26; u += 256) {
        int sp = (u >= 64 * 26), w2 = u - sp * 64 * 26, r = w2 / 26, c = w2 - r * 26;
        int cc = min(c, 24);
        cp_async16(sb + (uint32_t)((sp ? SVL : SVH) + r * 216 + c * 8) * 2,
                   (sp ? g_Vl : g_Vh) + ((size_t)bh * DFk + r) * Sk + cc * 8);
    }
    cp_commit();

    const int w = tid >> 5, lane = tid & 31, g = lane >> 2, q = lane & 3;
    const int bbb = bh >> 3, hh = bh & 7;

    cp_wait<0>();
    __syncthreads();

    const int nb = (w >= 3) ? 2 : 1;
    for (int bi = 0; bi < nb; bi++) {
        const int blk = bi ? (w - 3) : (12 - w);
        const int qr0 = blk * 16 + g;
        const int qr1 = qr0 + 8;
        const int KCW = blk + 1;

        uint32_t qah[4][4], qal[4][4];
        {
            const int r1c = min(qr1, Sk - 1);
            const bf16* Qh0 = g_Qh + ((size_t)bh * Sk + qr0) * DFk;
            const bf16* Qh1 = g_Qh + ((size_t)bh * Sk + r1c) * DFk;
            const bf16* Ql0 = g_Ql + ((size_t)bh * Sk + qr0) * DFk;
            const bf16* Ql1 = g_Ql + ((size_t)bh * Sk + r1c) * DFk;
#pragma unroll
            for (int kc = 0; kc < 4; kc++) {
                const int col = 16 * kc + 2 * q;
                qah[kc][0] = *(const uint32_t*)(Qh0 + col);
                qah[kc][1] = *(const uint32_t*)(Qh1 + col);
                qah[kc][2] = *(const uint32_t*)(Qh0 + col + 8);
                qah[kc][3] = *(const uint32_t*)(Qh1 + col + 8);
                qal[kc][0] = *(const uint32_t*)(Ql0 + col);
                qal[kc][1] = *(const uint32_t*)(Ql1 + col);
                qal[kc][2] = *(const uint32_t*)(Ql0 + col + 8);
                qal[kc][3] = *(const uint32_t*)(Ql1 + col + 8);
            }
        }

        float oa[8][4];
#pragma unroll
        for (int nv = 0; nv < 8; nv++)
            oa[nv][0] = oa[nv][1] = oa[nv][2] = oa[nv][3] = 0.f;
        float sum0 = 0.f, sum1 = 0.f;

        for (int kc = 0; kc < KCW; kc++) {
            const bool d1 = (16 * kc + 8 < Sk);
            float s0[4] = {0.f, 0.f, 0.f, 0.f};
            float s1[4] = {0.f, 0.f, 0.f, 0.f};
#pragma unroll
            for (int dfc = 0; dfc < 4; dfc++) {
                const int o0 = (16 * kc + g) * 72 + 16 * dfc + 2 * q;
                uint32_t kb0[2], kl0[2], kb1[2], kl1[2];
                kb0[0] = *(const uint32_t*)&smb[SKH + o0];
                kb0[1] = *(const uint32_t*)&smb[SKH + o0 + 8];
                kl0[0] = *(const uint32_t*)&smb[SKL + o0];
                kl0[1] = *(const uint32_t*)&smb[SKL + o0 + 8];
                if (d1) {
                    const int o1 = o0 + 8 * 72;
                    kb1[0] = *(const uint32_t*)&smb[SKH + o1];
                    kb1[1] = *(const uint32_t*)&smb[SKH + o1 + 8];
                    kl1[0] = *(const uint32_t*)&smb[SKL + o1];
                    kl1[1] = *(const uint32_t*)&smb[SKL + o1 + 8];
                }
                MMA16816(s0, qah[dfc], kb0);
                if (d1) MMA16816(s1, qah[dfc], kb1);
                MMA16816(s0, qah[dfc], kl0);
                if (d1) MMA16816(s1, qah[dfc], kl1);
                MMA16816(s0, qal[dfc], kb0);
                if (d1) MMA16816(s1, qal[dfc], kb1);
            }
            const int k0 = 16 * kc + 2 * q;
            s0[0] = fast_exp((k0     <= qr0) ? s0[0] * SCALE : -1e30f);
            s0[1] = fast_exp((k0 + 1 <= qr0) ? s0[1] * SCALE : -1e30f);
            s0[2] = fast_exp((k0     <= qr1) ? s0[2] * SCALE : -1e30f);
            s0[3] = fast_exp((k0 + 1 <= qr1) ? s0[3] * SCALE : -1e30f);
            sum0 += s0[0] + s0[1];
            sum1 += s0[2] + s0[3];
            if (d1) {
                const int k1 = k0 + 8;
                s1[0] = fast_exp((k1     <= qr0) ? s1[0] * SCALE : -1e30f);
                s1[1] = fast_exp((k1 + 1 <= qr0) ? s1[1] * SCALE : -1e30f);
                s1[2] = fast_exp((k1     <= qr1) ? s1[2] * SCALE : -1e30f);
                s1[3] = fast_exp((k1 + 1 <= qr1) ? s1[3] * SCALE : -1e30f);
                sum0 += s1[0] + s1[1];
                sum1 += s1[2] + s1[3];
            }
            uint32_t ph[4], pl[4];
            splitpack(s0[0], s0[1], ph[0], pl[0]);
            splitpack(s0[2], s0[3], ph[1], pl[1]);
            if (d1) {
                splitpack(s1[0], s1[1], ph[2], pl[2]);
                splitpack(s1[2], s1[3], ph[3], pl[3]);
            } else {
                ph[2] = ph[3] = pl[2] = pl[3] = 0u;
            }
#pragma unroll
            for (int nvp = 0; nvp < 4; nvp++) {
                const int nv0 = 2 * nvp, nv1 = nv0 + 1;
                const int o0 = (8 * nv0 + g) * 216 + 16 * kc + 2 * q;
                const int o1 = o0 + 8 * 216;
                uint32_t vb0[2], vl0[2], vb1[2], vl1[2];
                vb0[0] = *(const uint32_t*)&smb[SVH + o0];
                vb0[1] = *(const uint32_t*)&smb[SVH + o0 + 8];
                vl0[0] = *(const uint32_t*)&smb[SVL + o0];
                vl0[1] = *(const uint32_t*)&smb[SVL + o0 + 8];
                vb1[0] = *(const uint32_t*)&smb[SVH + o1];
                vb1[1] = *(const uint32_t*)&smb[SVH + o1 + 8];
                vl1[0] = *(const uint32_t*)&smb[SVL + o1];
                vl1[1] = *(const uint32_t*)&smb[SVL + o1 + 8];
                MMA16816(oa[nv0], ph, vb0);
                MMA16816(oa[nv1], ph, vb1);
                MMA16816(oa[nv0], ph, vl0);
                MMA16816(oa[nv1], ph, vl1);
                MMA16816(oa[nv0], pl, vb0);
                MMA16816(oa[nv1], pl, vb1);
            }
        }

        sum0 += __shfl_xor_sync(0xFFFFFFFFu, sum0, 1);
        sum0 += __shfl_xor_sync(0xFFFFFFFFu, sum0, 2);
        sum1 += __shfl_xor_sync(0xFFFFFFFFu, sum1, 1);
        sum1 += __shfl_xor_sync(0xFFFFFFFFu, sum1, 2);
        const float inv0 = (qr0 == 0) ? 0.f : 1.f / fmaxf(sum0, 1e-37f);
        const float inv1 = 1.f / fmaxf(sum1, 1e-37f);

#pragma unroll
        for (int nv = 0; nv < 8; nv++) {
            const int df = 8 * nv + 2 * q;
            {
                const float x0 = oa[nv][0] * inv0, x1 = oa[nv][1] * inv0;
                const size_t o = ((size_t)bbb * Sk + qr0) * Dk + hh * 64 + df;
                bf16 a = __float2bfloat16(x0);
                bf16 b = __float2bfloat16(x1);
                *(__nv_bfloat162*)&g_chi[o] = __halves2bfloat162(a, b);
                *(__nv_bfloat162*)&g_clo[o] = __halves2bfloat162(
                    __float2bfloat16(x0 - __bfloat162float(a)),
                    __float2bfloat16(x1 - __bfloat162float(b)));
            }
            if (qr1 < Sk) {
                const float x0 = oa[nv][2] * inv1, x1 = oa[nv][3] * inv1;
                const size_t o = ((size_t)bbb * Sk + qr1) * Dk + hh * 64 + df;
                bf16 a = __float2bfloat16(x0);
                bf16 b = __float2bfloat16(x1);
                *(__nv_bfloat162*)&g_chi[o] = __halves2bfloat162(a, b);
                *(__nv_bfloat162*)&g_clo[o] = __halves2bfloat162(
                    __float2bfloat16(x0 - __bfloat162float(a)),
                    __float2bfloat16(x1 - __bfloat162float(b)));
            }
        }
    }
}

// ---------------- launch ----------------
extern "C" void kernel_launch(void* const* d_in, const int* in_sizes, int n_in,
                              void* d_out, int out_size)
{
    const float* q  = (const float*)d_in[0];
    const float* k  = (const float*)d_in[1];
    const float* v  = (const float*)d_in[2];
    const float* Wq = (const float*)d_in[3];
    const float* bq = (const float*)d_in[4];
    const float* Wk = (const float*)d_in[5];
    const float* bk = (const float*)d_in[6];
    const float* Wv = (const float*)d_in[7];
    const float* bv = (const float*)d_in[8];
    const float* Wo = (const float*)d_in[9];
    const float* bo = (const float*)d_in[10];
    float* out = (float*)d_out;

    cvt_w_kernel<<<(CVTW_TOT + 255) / 256, 256>>>(Wq, Wk, Wv, Wo);

    cudaFuncSetAttribute(qkv_mma_kernel, cudaFuncAttributeMaxDynamicSharedMemorySize,
                         GEMM_SMEM_A);
    qkv_mma_kernel<<<dim3(Dk / 128, ROWS / 128, 3), 256, GEMM_SMEM_A>>>(q, k, v,
                                                                        bq, bk, bv);

    cudaFuncSetAttribute(attn_mma_kernel, cudaFuncAttributeMaxDynamicSharedMemorySize,
                         ATTN_SMEM);
    attn_mma_kernel<<<Bk * Hk, 256, ATTN_SMEM>>>();

    cudaFuncSetAttribute(out_mma_kernel, cudaFuncAttributeMaxDynamicSharedMemorySize,
                         GEMM_SMEM_B);
    out_mma_kernel<<<dim3(Dk / 256, ROWS / 128, 1), 512, GEMM_SMEM_B>>>(bo, out);
}